// round 1
// baseline (speedup 1.0000x reference)
#include <cuda_runtime.h>
#include <cuda_bf16.h>
#include <math.h>

#define BB 2
#define SS 4096
#define DM 768
#define NH 12
#define FF 3072
#define WIN 64
#define HD 64
#define NC (SS / WIN)      // 64 chunks
#define MROWS (BB * SS)    // 8192

// ---------------- scratch (allocation-free: __device__ globals) ----------------
__device__ float g_q[MROWS * DM];
__device__ float g_k[MROWS * DM];
__device__ float g_v[MROWS * DM];
__device__ float g_attn[MROWS * DM];
__device__ float g_x1[MROWS * DM];
__device__ float g_hid[MROWS * FF];
__device__ float g_ff[MROWS * DM];

// ---------------- GELU (tanh approximation, matches jax.nn.gelu default) -------
__device__ __forceinline__ float gelu_tanh(float x) {
    const float c = 0.7978845608028654f;  // sqrt(2/pi)
    float x3 = x * x * x;
    return 0.5f * x * (1.0f + tanhf(c * (x + 0.044715f * x3)));
}

// ---------------- generic fp32 GEMM: C = A[M,K] @ W[K,N] + bias, optional gelu --
#define TS 64
#define KT 16
__global__ void gemm_kernel(const float* __restrict__ A,
                            const float* __restrict__ W,
                            const float* __restrict__ bias,
                            float* __restrict__ C,
                            int M, int K, int N, int act) {
    __shared__ float As[KT][TS + 1];
    __shared__ float Bs[KT][TS + 1];
    int tx = threadIdx.x;            // 0..15
    int ty = threadIdx.y;            // 0..15
    int t  = ty * 16 + tx;           // 0..255
    int bm = blockIdx.y * TS;
    int bn = blockIdx.x * TS;

    float acc[4][4] = {};

    for (int k0 = 0; k0 < K; k0 += KT) {
        #pragma unroll
        for (int e = t; e < TS * KT; e += 256) {
            int m  = e >> 4, kk = e & 15;
            As[kk][m] = A[(size_t)(bm + m) * K + k0 + kk];
            int kk2 = e >> 6, n = e & 63;
            Bs[kk2][n] = W[(size_t)(k0 + kk2) * N + bn + n];
        }
        __syncthreads();
        #pragma unroll
        for (int kk = 0; kk < KT; kk++) {
            float a[4], b[4];
            #pragma unroll
            for (int u = 0; u < 4; u++) a[u] = As[kk][ty * 4 + u];
            #pragma unroll
            for (int u = 0; u < 4; u++) b[u] = Bs[kk][tx * 4 + u];
            #pragma unroll
            for (int i = 0; i < 4; i++)
                #pragma unroll
                for (int j = 0; j < 4; j++)
                    acc[i][j] = fmaf(a[i], b[j], acc[i][j]);
        }
        __syncthreads();
    }

    #pragma unroll
    for (int i = 0; i < 4; i++) {
        int m = bm + ty * 4 + i;
        #pragma unroll
        for (int j = 0; j < 4; j++) {
            int n = bn + tx * 4 + j;
            float val = acc[i][j] + bias[n];
            if (act) val = gelu_tanh(val);
            C[(size_t)m * N + n] = val;
        }
    }
}

// ---------------- sliding-window attention ------------------------------------
// one block per (chunk, head, batch); 256 threads = 8 warps, 8 q-rows per warp
#define KSTR 65
__global__ void attn_kernel(const float* __restrict__ q,
                            const float* __restrict__ k,
                            const float* __restrict__ v,
                            float* __restrict__ out) {
    extern __shared__ float sm[];
    float* sq = sm;                    // 64 x 64
    float* sk = sq + 64 * 64;          // 192 x KSTR
    float* sv = sk + 192 * KSTR;       // 192 x KSTR
    float* ss = sv + 192 * KSTR;       // 64 x 192 (probs)

    int c = blockIdx.x, h = blockIdx.y, b = blockIdx.z;
    int tid = threadIdx.x;
    const float scale = 0.125f;        // 1/sqrt(64)

    // load q (scaled)
    for (int idx = tid; idx < 64 * 64; idx += 256) {
        int i = idx >> 6, d = idx & 63;
        sq[idx] = q[((size_t)b * SS + c * 64 + i) * DM + h * HD + d] * scale;
    }
    // load k, v window (192 positions, zero-padded at sequence edges)
    for (int idx = tid; idx < 192 * 64; idx += 256) {
        int j = idx >> 6, d = idx & 63;
        int g = c * 64 - 64 + j;
        float kv = 0.f, vv = 0.f;
        if (g >= 0 && g < SS) {
            size_t off = ((size_t)b * SS + g) * DM + h * HD + d;
            kv = k[off];
            vv = v[off];
        }
        sk[j * KSTR + d] = kv;
        sv[j * KSTR + d] = vv;
    }
    __syncthreads();

    int warp = tid >> 5, lane = tid & 31;
    #pragma unroll 1
    for (int rr = 0; rr < 8; rr++) {
        int i = warp * 8 + rr;
        const float* qi = sq + i * 64;

        // each lane computes 6 score columns: j = lane + 32*t
        float sc[6];
        float m = -INFINITY;
        #pragma unroll
        for (int tt = 0; tt < 6; tt++) {
            int j = lane + 32 * tt;
            const float* kj = sk + j * KSTR;
            float acc = 0.f;
            #pragma unroll
            for (int d = 0; d < 64; d++) acc = fmaf(qi[d], kj[d], acc);
            int g = c * 64 - 64 + j;
            bool valid = (j >= i) && (j <= i + 2 * WIN) && (g >= 0) && (g < SS);
            acc = valid ? acc : -INFINITY;
            sc[tt] = acc;
            m = fmaxf(m, acc);
        }
        #pragma unroll
        for (int o = 16; o > 0; o >>= 1) m = fmaxf(m, __shfl_xor_sync(0xffffffffu, m, o));
        float sum = 0.f;
        #pragma unroll
        for (int tt = 0; tt < 6; tt++) {
            float e = __expf(sc[tt] - m);
            sc[tt] = e;
            sum += e;
        }
        #pragma unroll
        for (int o = 16; o > 0; o >>= 1) sum += __shfl_xor_sync(0xffffffffu, sum, o);
        float inv = 1.0f / sum;
        #pragma unroll
        for (int tt = 0; tt < 6; tt++) ss[i * 192 + lane + 32 * tt] = sc[tt] * inv;
        __syncwarp();

        // PV: lane owns output dims {lane, lane+32} -> conflict-free smem reads,
        // coalesced global stores
        float o0 = 0.f, o1 = 0.f;
        #pragma unroll 4
        for (int j = 0; j < 192; j++) {
            float p = ss[i * 192 + j];
            o0 = fmaf(p, sv[j * KSTR + lane], o0);
            o1 = fmaf(p, sv[j * KSTR + lane + 32], o1);
        }
        size_t ob = ((size_t)b * SS + c * 64 + i) * DM + h * HD;
        out[ob + lane]      = o0;
        out[ob + lane + 32] = o1;
    }
}

// ---------------- fused residual add + LayerNorm -------------------------------
__global__ void add_ln_kernel(const float* __restrict__ a,
                              const float* __restrict__ r,
                              const float* __restrict__ g,
                              const float* __restrict__ beta,
                              float* __restrict__ out) {
    int row = blockIdx.x;
    int tid = threadIdx.x;              // 256
    __shared__ float vals[DM];
    __shared__ float red[256];
    __shared__ float s_mu, s_rstd;

    const float* pa = a + (size_t)row * DM;
    const float* pr = r + (size_t)row * DM;

    float local = 0.f;
    for (int i = tid; i < DM; i += 256) {
        float vv = pa[i] + pr[i];
        vals[i] = vv;
        local += vv;
    }
    red[tid] = local;
    __syncthreads();
    for (int s = 128; s > 0; s >>= 1) {
        if (tid < s) red[tid] += red[tid + s];
        __syncthreads();
    }
    if (tid == 0) s_mu = red[0] / DM;
    __syncthreads();
    float mu = s_mu;

    local = 0.f;
    for (int i = tid; i < DM; i += 256) {
        float dv = vals[i] - mu;
        local += dv * dv;
    }
    red[tid] = local;
    __syncthreads();
    for (int s = 128; s > 0; s >>= 1) {
        if (tid < s) red[tid] += red[tid + s];
        __syncthreads();
    }
    if (tid == 0) s_rstd = rsqrtf(red[0] / DM + 1e-5f);
    __syncthreads();
    float rstd = s_rstd;

    float* po = out + (size_t)row * DM;
    for (int i = tid; i < DM; i += 256) {
        po[i] = (vals[i] - mu) * rstd * g[i] + beta[i];
    }
}

// ---------------- launch --------------------------------------------------------
extern "C" void kernel_launch(void* const* d_in, const int* in_sizes, int n_in,
                              void* d_out, int out_size) {
    const float* x     = (const float*)d_in[0];
    const float* Wq    = (const float*)d_in[1];
    const float* bq    = (const float*)d_in[2];
    const float* Wk    = (const float*)d_in[3];
    const float* bk    = (const float*)d_in[4];
    const float* Wv    = (const float*)d_in[5];
    const float* bv    = (const float*)d_in[6];
    const float* ln1_g = (const float*)d_in[7];
    const float* ln1_b = (const float*)d_in[8];
    const float* W1    = (const float*)d_in[9];
    const float* b1    = (const float*)d_in[10];
    const float* W2    = (const float*)d_in[11];
    const float* b2    = (const float*)d_in[12];
    const float* ln2_g = (const float*)d_in[13];
    const float* ln2_b = (const float*)d_in[14];
    float* out = (float*)d_out;

    float *q, *k, *v, *attn, *x1, *hid, *ff;
    cudaGetSymbolAddress((void**)&q,    g_q);
    cudaGetSymbolAddress((void**)&k,    g_k);
    cudaGetSymbolAddress((void**)&v,    g_v);
    cudaGetSymbolAddress((void**)&attn, g_attn);
    cudaGetSymbolAddress((void**)&x1,   g_x1);
    cudaGetSymbolAddress((void**)&hid,  g_hid);
    cudaGetSymbolAddress((void**)&ff,   g_ff);

    dim3 gThreads(16, 16);

    // QKV projections
    {
        dim3 grid(DM / TS, MROWS / TS);
        gemm_kernel<<<grid, gThreads>>>(x, Wq, bq, q, MROWS, DM, DM, 0);
        gemm_kernel<<<grid, gThreads>>>(x, Wk, bk, k, MROWS, DM, DM, 0);
        gemm_kernel<<<grid, gThreads>>>(x, Wv, bv, v, MROWS, DM, DM, 0);
    }

    // sliding window attention
    {
        int smem = (64 * 64 + 2 * 192 * KSTR + 64 * 192) * sizeof(float);
        cudaFuncSetAttribute(attn_kernel, cudaFuncAttributeMaxDynamicSharedMemorySize, smem);
        dim3 grid(NC, NH, BB);
        attn_kernel<<<grid, 256, smem>>>(q, k, v, attn);
    }

    // x1 = LN(attn + x)
    add_ln_kernel<<<MROWS, 256>>>(attn, x, ln1_g, ln1_b, x1);

    // FFN
    {
        dim3 grid1(FF / TS, MROWS / TS);
        gemm_kernel<<<grid1, gThreads>>>(x1, W1, b1, hid, MROWS, DM, FF, 1);
        dim3 grid2(DM / TS, MROWS / TS);
        gemm_kernel<<<grid2, gThreads>>>(hid, W2, b2, ff, MROWS, FF, DM, 0);
    }

    // out = LN(ff + x1)
    add_ln_kernel<<<MROWS, 256>>>(ff, x1, ln2_g, ln2_b, out);
}

// round 3
// speedup vs baseline: 2.9316x; 2.9316x over previous
#include <cuda_runtime.h>
#include <cuda_bf16.h>
#include <math.h>
#include <cstdint>

#define BB 2
#define SS 4096
#define DM 768
#define NH 12
#define FF 3072
#define WIN 64
#define HD 64
#define NC (SS / WIN)
#define MROWS (BB * SS)    // 8192
#define QKVN (3 * DM)      // 2304

// ================= helpers =================
__device__ __forceinline__ uint32_t smem_to_u32(const void* p) {
    uint32_t a;
    asm("{ .reg .u64 t; cvta.to.shared.u64 t, %1; cvt.u32.u64 %0, t; }" : "=r"(a) : "l"(p));
    return a;
}
#define SMEM_SWIZZLE_128B(o) ((o) ^ (((o) >> 3) & 0x70))

__device__ __forceinline__ void ldsm_x4(uint32_t r[4], uint32_t addr) {
    asm volatile("ldmatrix.sync.aligned.m8n8.x4.shared.b16 {%0,%1,%2,%3}, [%4];"
        : "=r"(r[0]), "=r"(r[1]), "=r"(r[2]), "=r"(r[3]) : "r"(addr));
}
__device__ __forceinline__ void mma_bf16(float c[4], const uint32_t a[4],
                                         uint32_t b0, uint32_t b1) {
    asm volatile("mma.sync.aligned.m16n8k16.row.col.f32.bf16.bf16.f32 "
        "{%0,%1,%2,%3}, {%4,%5,%6,%7}, {%8,%9}, {%0,%1,%2,%3};"
        : "+f"(c[0]), "+f"(c[1]), "+f"(c[2]), "+f"(c[3])
        : "r"(a[0]), "r"(a[1]), "r"(a[2]), "r"(a[3]), "r"(b0), "r"(b1));
}

// ================= scratch =================
__device__ float g_qkv[MROWS * QKVN];
__device__ float g_attn[MROWS * DM];
__device__ float g_x1[MROWS * DM];
__device__ float g_ff[MROWS * DM];
__device__ float g_bqkv[QKVN];
__device__ __nv_bfloat16 g_xh[MROWS * DM],  g_xl[MROWS * DM];
__device__ __nv_bfloat16 g_x1h[MROWS * DM], g_x1l[MROWS * DM];
__device__ __nv_bfloat16 g_hidh[MROWS * FF], g_hidl[MROWS * FF];
__device__ __nv_bfloat16 g_wqkvh[QKVN * DM], g_wqkvl[QKVN * DM];
__device__ __nv_bfloat16 g_w1h[FF * DM], g_w1l[FF * DM];
__device__ __nv_bfloat16 g_w2h[DM * FF], g_w2l[DM * FF];

__device__ __forceinline__ float gelu_tanh(float x) {
    const float c = 0.7978845608028654f;
    float x3 = x * x * x;
    return 0.5f * x * (1.0f + tanhf(c * (x + 0.044715f * x3)));
}
__device__ __forceinline__ void split_bf16(float v, __nv_bfloat16& h, __nv_bfloat16& l) {
    h = __float2bfloat16(v);
    l = __float2bfloat16(v - __bfloat162float(h));
}

// ========== elementwise fp32 -> bf16 hi/lo ==========
__global__ void split_convert(const float* __restrict__ in,
                              __nv_bfloat16* __restrict__ hi,
                              __nv_bfloat16* __restrict__ lo, int n4) {
    int i = blockIdx.x * blockDim.x + threadIdx.x;
    if (i >= n4) return;
    float4 v = reinterpret_cast<const float4*>(in)[i];
    __nv_bfloat16 h0,l0,h1,l1,h2,l2,h3,l3;
    split_bf16(v.x, h0, l0); split_bf16(v.y, h1, l1);
    split_bf16(v.z, h2, l2); split_bf16(v.w, h3, l3);
    reinterpret_cast<__nv_bfloat162*>(hi)[i*2+0] = __nv_bfloat162(h0, h1);
    reinterpret_cast<__nv_bfloat162*>(hi)[i*2+1] = __nv_bfloat162(h2, h3);
    reinterpret_cast<__nv_bfloat162*>(lo)[i*2+0] = __nv_bfloat162(l0, l1);
    reinterpret_cast<__nv_bfloat162*>(lo)[i*2+1] = __nv_bfloat162(l2, l3);
}

// ========== transpose + split: W[K,N] -> Wt_hi/lo[N,K] ==========
__global__ void transpose_convert(const float* __restrict__ W,
                                  __nv_bfloat16* __restrict__ Th,
                                  __nv_bfloat16* __restrict__ Tl, int K, int N) {
    __shared__ float t[32][33];
    int n0 = blockIdx.x * 32, k0 = blockIdx.y * 32;
    int tx = threadIdx.x, ty = threadIdx.y;   // 32 x 8
    #pragma unroll
    for (int i = 0; i < 4; i++)
        t[ty + i*8][tx] = W[(size_t)(k0 + ty + i*8) * N + n0 + tx];
    __syncthreads();
    #pragma unroll
    for (int i = 0; i < 4; i++) {
        float v = t[tx][ty + i*8];
        __nv_bfloat16 h, l; split_bf16(v, h, l);
        size_t o = (size_t)(n0 + ty + i*8) * K + k0 + tx;
        Th[o] = h; Tl[o] = l;
    }
}

__global__ void pack_bias3(const float* __restrict__ a, const float* __restrict__ b,
                           const float* __restrict__ c, float* __restrict__ o) {
    int i = blockIdx.x * blockDim.x + threadIdx.x;
    if (i >= QKVN) return;
    o[i] = (i < DM) ? a[i] : (i < 2 * DM) ? b[i - DM] : c[i - 2 * DM];
}

// ========== HMMA GEMM: C[M,N] = A[M,K] @ Bt[N,K]^T + bias ==========
// 3xBF16 split: Ah*Bh + Ah*Bl + Al*Bh, fp32 accumulate.
// CTA tile 128x128, 8 warps of 32x64, K staged 64-wide, double buffered.
#define STAGE_BYTES 65536
#define GEMM_SMEM (2 * STAGE_BYTES)
__global__ void __launch_bounds__(256, 1)
tc_gemm(const __nv_bfloat16* __restrict__ Ah, const __nv_bfloat16* __restrict__ Al,
        const __nv_bfloat16* __restrict__ Bh, const __nv_bfloat16* __restrict__ Bl,
        const float* __restrict__ bias,
        float* __restrict__ outF,
        __nv_bfloat16* __restrict__ outHi, __nv_bfloat16* __restrict__ outLo,
        int M, int N, int K, int act) {
    extern __shared__ char smem[];
    const uint32_t tiles = smem_to_u32(smem);
    const int tid = threadIdx.x;
    const int wid = tid >> 5;
    const int lane = tid & 31;
    const int warpM = wid >> 1;          // 0..3
    const int warpN = wid & 1;           // 0..1
    const int bm = blockIdx.y * 128;
    const int bn = blockIdx.x * 128;
    const int NB = K >> 6;

    const __nv_bfloat16* srcs[4] = {Ah, Al, Bh, Bl};

    auto stage = [&](int kb, int s) {
        #pragma unroll
        for (int t = 0; t < 4; t++) {
            const __nv_bfloat16* src = srcs[t];
            const int rbase = (t < 2) ? bm : bn;
            const uint32_t sb = tiles + (uint32_t)s * STAGE_BYTES + (uint32_t)t * 16384u;
            #pragma unroll
            for (int i = 0; i < 4; i++) {
                int chunk = tid + i * 256;
                int row = chunk >> 3;
                int c16 = chunk & 7;
                uint32_t off = (uint32_t)(row * 128 + c16 * 16);
                uint32_t dst = sb + SMEM_SWIZZLE_128B(off);
                const void* g = src + (size_t)(rbase + row) * K + kb * 64 + c16 * 8;
                asm volatile("cp.async.cg.shared.global [%0], [%1], 16;" :: "r"(dst), "l"(g));
            }
        }
        asm volatile("cp.async.commit_group;" ::: "memory");
    };

    float c[2][8][4] = {};

    stage(0, 0);
    if (NB > 1) stage(1, 1);

    const int lrow = lane & 15;
    const int lchunk = lane >> 4;

    for (int kb = 0; kb < NB; kb++) {
        const int s = kb & 1;
        if (kb + 1 < NB) asm volatile("cp.async.wait_group 1;" ::: "memory");
        else             asm volatile("cp.async.wait_group 0;" ::: "memory");
        __syncthreads();
        const uint32_t base_s = tiles + (uint32_t)s * STAGE_BYTES;

        #pragma unroll
        for (int ks = 0; ks < 4; ks++) {
            uint32_t ah[2][4], al2[2][4];
            #pragma unroll
            for (int mt = 0; mt < 2; mt++) {
                uint32_t off = (uint32_t)((warpM * 32 + mt * 16 + lrow) * 128 + ks * 32 + lchunk * 16);
                uint32_t sw = SMEM_SWIZZLE_128B(off);
                ldsm_x4(ah[mt],  base_s + sw);
                ldsm_x4(al2[mt], base_s + 16384u + sw);
            }
            #pragma unroll
            for (int np = 0; np < 4; np++) {
                uint32_t off = (uint32_t)((warpN * 64 + np * 16 + lrow) * 128 + ks * 32 + lchunk * 16);
                uint32_t sw = SMEM_SWIZZLE_128B(off);
                uint32_t bh[4], bl[4];
                ldsm_x4(bh, base_s + 32768u + sw);
                ldsm_x4(bl, base_s + 49152u + sw);
                #pragma unroll
                for (int mt = 0; mt < 2; mt++) {
                    mma_bf16(c[mt][2*np],   ah[mt],  bh[0], bh[2]);
                    mma_bf16(c[mt][2*np+1], ah[mt],  bh[1], bh[3]);
                    mma_bf16(c[mt][2*np],   ah[mt],  bl[0], bl[2]);
                    mma_bf16(c[mt][2*np+1], ah[mt],  bl[1], bl[3]);
                    mma_bf16(c[mt][2*np],   al2[mt], bh[0], bh[2]);
                    mma_bf16(c[mt][2*np+1], al2[mt], bh[1], bh[3]);
                }
            }
        }
        __syncthreads();
        if (kb + 2 < NB) stage(kb + 2, s);
    }

    // epilogue: regs -> smem (padded) -> coalesced global
    float* sD = reinterpret_cast<float*>(smem);   // 128 x 129
    #pragma unroll
    for (int mt = 0; mt < 2; mt++) {
        #pragma unroll
        for (int nt = 0; nt < 8; nt++) {
            int r0 = warpM * 32 + mt * 16 + (lane >> 2);
            int col = warpN * 64 + nt * 8 + (lane & 3) * 2;
            sD[r0 * 129 + col]           = c[mt][nt][0];
            sD[r0 * 129 + col + 1]       = c[mt][nt][1];
            sD[(r0 + 8) * 129 + col]     = c[mt][nt][2];
            sD[(r0 + 8) * 129 + col + 1] = c[mt][nt][3];
        }
    }
    __syncthreads();

    for (int idx = tid; idx < 128 * 128; idx += 256) {
        int r = idx >> 7, cc = idx & 127;
        float v = sD[r * 129 + cc] + bias[bn + cc];
        if (act) v = gelu_tanh(v);
        size_t go = (size_t)(bm + r) * N + bn + cc;
        if (outF) outF[go] = v;
        if (outHi) {
            __nv_bfloat16 h, l; split_bf16(v, h, l);
            outHi[go] = h; outLo[go] = l;
        }
    }
}

// ================= sliding-window attention (packed qkv input) =================
#define KSTR 65
__global__ void attn_kernel(const float* __restrict__ qkv,
                            float* __restrict__ out) {
    extern __shared__ float sm[];
    float* sq = sm;
    float* sk = sq + 64 * 64;
    float* sv = sk + 192 * KSTR;
    float* ss = sv + 192 * KSTR;

    int c = blockIdx.x, h = blockIdx.y, b = blockIdx.z;
    int tid = threadIdx.x;
    const float scale = 0.125f;

    for (int idx = tid; idx < 64 * 64; idx += 256) {
        int i = idx >> 6, d = idx & 63;
        sq[idx] = qkv[((size_t)b * SS + c * 64 + i) * QKVN + h * HD + d] * scale;
    }
    for (int idx = tid; idx < 192 * 64; idx += 256) {
        int j = idx >> 6, d = idx & 63;
        int g = c * 64 - 64 + j;
        float kv = 0.f, vv = 0.f;
        if (g >= 0 && g < SS) {
            size_t off = ((size_t)b * SS + g) * QKVN + h * HD + d;
            kv = qkv[off + DM];
            vv = qkv[off + 2 * DM];
        }
        sk[j * KSTR + d] = kv;
        sv[j * KSTR + d] = vv;
    }
    __syncthreads();

    int warp = tid >> 5, lane = tid & 31;
    #pragma unroll 1
    for (int rr = 0; rr < 8; rr++) {
        int i = warp * 8 + rr;
        const float* qi = sq + i * 64;
        float sc[6];
        float m = -INFINITY;
        #pragma unroll
        for (int tt = 0; tt < 6; tt++) {
            int j = lane + 32 * tt;
            const float* kj = sk + j * KSTR;
            float acc = 0.f;
            #pragma unroll
            for (int d = 0; d < 64; d++) acc = fmaf(qi[d], kj[d], acc);
            int g = c * 64 - 64 + j;
            bool valid = (j >= i) && (j <= i + 2 * WIN) && (g >= 0) && (g < SS);
            acc = valid ? acc : -INFINITY;
            sc[tt] = acc;
            m = fmaxf(m, acc);
        }
        #pragma unroll
        for (int o = 16; o > 0; o >>= 1) m = fmaxf(m, __shfl_xor_sync(0xffffffffu, m, o));
        float sum = 0.f;
        #pragma unroll
        for (int tt = 0; tt < 6; tt++) { float e = __expf(sc[tt] - m); sc[tt] = e; sum += e; }
        #pragma unroll
        for (int o = 16; o > 0; o >>= 1) sum += __shfl_xor_sync(0xffffffffu, sum, o);
        float inv = 1.0f / sum;
        #pragma unroll
        for (int tt = 0; tt < 6; tt++) ss[i * 192 + lane + 32 * tt] = sc[tt] * inv;
        __syncwarp();

        float o0 = 0.f, o1 = 0.f;
        #pragma unroll 4
        for (int j = 0; j < 192; j++) {
            float p = ss[i * 192 + j];
            o0 = fmaf(p, sv[j * KSTR + lane], o0);
            o1 = fmaf(p, sv[j * KSTR + lane + 32], o1);
        }
        size_t ob = ((size_t)b * SS + c * 64 + i) * DM + h * HD;
        out[ob + lane]      = o0;
        out[ob + lane + 32] = o1;
    }
}

// ================= fused residual + LayerNorm (+ optional bf16 hi/lo emit) ======
__global__ void add_ln_kernel(const float* __restrict__ a,
                              const float* __restrict__ r,
                              const float* __restrict__ g,
                              const float* __restrict__ beta,
                              float* __restrict__ out,
                              __nv_bfloat16* __restrict__ outHi,
                              __nv_bfloat16* __restrict__ outLo) {
    int row = blockIdx.x;
    int tid = threadIdx.x;
    __shared__ float vals[DM];
    __shared__ float red[256];
    __shared__ float s_mu, s_rstd;

    const float* pa = a + (size_t)row * DM;
    const float* pr = r + (size_t)row * DM;

    float local = 0.f;
    for (int i = tid; i < DM; i += 256) {
        float vv = pa[i] + pr[i];
        vals[i] = vv;
        local += vv;
    }
    red[tid] = local;
    __syncthreads();
    for (int s = 128; s > 0; s >>= 1) { if (tid < s) red[tid] += red[tid + s]; __syncthreads(); }
    if (tid == 0) s_mu = red[0] / DM;
    __syncthreads();
    float mu = s_mu;

    local = 0.f;
    for (int i = tid; i < DM; i += 256) { float dv = vals[i] - mu; local += dv * dv; }
    red[tid] = local;
    __syncthreads();
    for (int s = 128; s > 0; s >>= 1) { if (tid < s) red[tid] += red[tid + s]; __syncthreads(); }
    if (tid == 0) s_rstd = rsqrtf(red[0] / DM + 1e-5f);
    __syncthreads();
    float rstd = s_rstd;

    for (int i = tid; i < DM; i += 256) {
        float y = (vals[i] - mu) * rstd * g[i] + beta[i];
        size_t o = (size_t)row * DM + i;
        out[o] = y;
        if (outHi) {
            __nv_bfloat16 h, l; split_bf16(y, h, l);
            outHi[o] = h; outLo[o] = l;
        }
    }
}

// ================= launch =================
extern "C" void kernel_launch(void* const* d_in, const int* in_sizes, int n_in,
                              void* d_out, int out_size) {
    const float* x     = (const float*)d_in[0];
    const float* Wq    = (const float*)d_in[1];
    const float* bq    = (const float*)d_in[2];
    const float* Wk    = (const float*)d_in[3];
    const float* bk    = (const float*)d_in[4];
    const float* Wv    = (const float*)d_in[5];
    const float* bv    = (const float*)d_in[6];
    const float* ln1_g = (const float*)d_in[7];
    const float* ln1_b = (const float*)d_in[8];
    const float* W1    = (const float*)d_in[9];
    const float* b1    = (const float*)d_in[10];
    const float* W2    = (const float*)d_in[11];
    const float* b2    = (const float*)d_in[12];
    const float* ln2_g = (const float*)d_in[13];
    const float* ln2_b = (const float*)d_in[14];
    float* out = (float*)d_out;

    float *qkv, *attn, *x1, *ff, *bqkv;
    __nv_bfloat16 *xh, *xl, *x1h, *x1l, *hidh, *hidl;
    __nv_bfloat16 *wqkvh, *wqkvl, *w1h, *w1l, *w2h, *w2l;
    cudaGetSymbolAddress((void**)&qkv, g_qkv);   cudaGetSymbolAddress((void**)&attn, g_attn);
    cudaGetSymbolAddress((void**)&x1, g_x1);     cudaGetSymbolAddress((void**)&ff, g_ff);
    cudaGetSymbolAddress((void**)&bqkv, g_bqkv);
    cudaGetSymbolAddress((void**)&xh, g_xh);     cudaGetSymbolAddress((void**)&xl, g_xl);
    cudaGetSymbolAddress((void**)&x1h, g_x1h);   cudaGetSymbolAddress((void**)&x1l, g_x1l);
    cudaGetSymbolAddress((void**)&hidh, g_hidh); cudaGetSymbolAddress((void**)&hidl, g_hidl);
    cudaGetSymbolAddress((void**)&wqkvh, g_wqkvh); cudaGetSymbolAddress((void**)&wqkvl, g_wqkvl);
    cudaGetSymbolAddress((void**)&w1h, g_w1h);   cudaGetSymbolAddress((void**)&w1l, g_w1l);
    cudaGetSymbolAddress((void**)&w2h, g_w2h);   cudaGetSymbolAddress((void**)&w2l, g_w2l);

    cudaFuncSetAttribute(tc_gemm, cudaFuncAttributeMaxDynamicSharedMemorySize, GEMM_SMEM);

    // ---- convert inputs ----
    {
        int n4 = MROWS * DM / 4;
        split_convert<<<(n4 + 255) / 256, 256>>>(x, xh, xl, n4);
        pack_bias3<<<(QKVN + 255) / 256, 256>>>(bq, bk, bv, bqkv);
        dim3 tb(32, 8);
        // packed W^T: rows [0,768)=Wq^T, [768,1536)=Wk^T, [1536,2304)=Wv^T
        transpose_convert<<<dim3(DM / 32, DM / 32), tb>>>(Wq, wqkvh,                 wqkvl,                 DM, DM);
        transpose_convert<<<dim3(DM / 32, DM / 32), tb>>>(Wk, wqkvh + DM * DM,       wqkvl + DM * DM,       DM, DM);
        transpose_convert<<<dim3(DM / 32, DM / 32), tb>>>(Wv, wqkvh + 2 * DM * DM,   wqkvl + 2 * DM * DM,   DM, DM);
        transpose_convert<<<dim3(FF / 32, DM / 32), tb>>>(W1, w1h, w1l, DM, FF);
        transpose_convert<<<dim3(DM / 32, FF / 32), tb>>>(W2, w2h, w2l, FF, DM);
    }

    // ---- fused QKV projection: [8192,768] @ [768,2304] ----
    {
        dim3 grid(QKVN / 128, MROWS / 128);
        tc_gemm<<<grid, 256, GEMM_SMEM>>>(xh, xl, wqkvh, wqkvl, bqkv, qkv,
                                          nullptr, nullptr, MROWS, QKVN, DM, 0);
    }

    // ---- attention ----
    {
        int smem = (64 * 64 + 2 * 192 * KSTR + 64 * 192) * sizeof(float);
        cudaFuncSetAttribute(attn_kernel, cudaFuncAttributeMaxDynamicSharedMemorySize, smem);
        dim3 grid(NC, NH, BB);
        attn_kernel<<<grid, 256, smem>>>(qkv, attn);
    }

    // ---- x1 = LN(attn + x), emit bf16 hi/lo ----
    add_ln_kernel<<<MROWS, 256>>>(attn, x, ln1_g, ln1_b, x1, x1h, x1l);

    // ---- FFN ----
    {
        dim3 grid1(FF / 128, MROWS / 128);
        tc_gemm<<<grid1, 256, GEMM_SMEM>>>(x1h, x1l, w1h, w1l, b1, nullptr,
                                           hidh, hidl, MROWS, FF, DM, 1);
        dim3 grid2(DM / 128, MROWS / 128);
        tc_gemm<<<grid2, 256, GEMM_SMEM>>>(hidh, hidl, w2h, w2l, b2, ff,
                                           nullptr, nullptr, MROWS, DM, FF, 0);
    }

    // ---- out = LN(ff + x1) ----
    add_ln_kernel<<<MROWS, 256>>>(ff, x1, ln2_g, ln2_b, out, nullptr, nullptr);
}

// round 4
// speedup vs baseline: 3.5802x; 1.2212x over previous
#include <cuda_runtime.h>
#include <cuda_bf16.h>
#include <math.h>
#include <cstdint>

#define BB 2
#define SS 4096
#define DM 768
#define NH 12
#define FF 3072
#define WIN 64
#define HD 64
#define NC (SS / WIN)
#define MROWS (BB * SS)    // 8192
#define QKVN (3 * DM)      // 2304

// ================= helpers =================
__device__ __forceinline__ uint32_t smem_to_u32(const void* p) {
    uint32_t a;
    asm("{ .reg .u64 t; cvta.to.shared.u64 t, %1; cvt.u32.u64 %0, t; }" : "=r"(a) : "l"(p));
    return a;
}
#define SMEM_SWIZZLE_128B(o) ((o) ^ (((o) >> 3) & 0x70))

__device__ __forceinline__ void ldsm_x4(uint32_t r[4], uint32_t addr) {
    asm volatile("ldmatrix.sync.aligned.m8n8.x4.shared.b16 {%0,%1,%2,%3}, [%4];"
        : "=r"(r[0]), "=r"(r[1]), "=r"(r[2]), "=r"(r[3]) : "r"(addr));
}
__device__ __forceinline__ void mma_bf16(float c[4], const uint32_t a[4],
                                         uint32_t b0, uint32_t b1) {
    asm volatile("mma.sync.aligned.m16n8k16.row.col.f32.bf16.bf16.f32 "
        "{%0,%1,%2,%3}, {%4,%5,%6,%7}, {%8,%9}, {%0,%1,%2,%3};"
        : "+f"(c[0]), "+f"(c[1]), "+f"(c[2]), "+f"(c[3])
        : "r"(a[0]), "r"(a[1]), "r"(a[2]), "r"(a[3]), "r"(b0), "r"(b1));
}

// ================= scratch =================
__device__ float g_qkv[MROWS * QKVN];
__device__ float g_attn[MROWS * DM];
__device__ float g_x1[MROWS * DM];
__device__ float g_ff[MROWS * DM];
__device__ float g_bqkv[QKVN];
__device__ __nv_bfloat16 g_xh[MROWS * DM],  g_xl[MROWS * DM];
__device__ __nv_bfloat16 g_x1h[MROWS * DM], g_x1l[MROWS * DM];
__device__ __nv_bfloat16 g_hidh[MROWS * FF], g_hidl[MROWS * FF];
__device__ __nv_bfloat16 g_wqkvh[QKVN * DM], g_wqkvl[QKVN * DM];
__device__ __nv_bfloat16 g_w1h[FF * DM], g_w1l[FF * DM];
__device__ __nv_bfloat16 g_w2h[DM * FF], g_w2l[DM * FF];

__device__ __forceinline__ float gelu_tanh(float x) {
    const float c = 0.7978845608028654f;
    float x3 = x * x * x;
    return 0.5f * x * (1.0f + tanhf(c * (x + 0.044715f * x3)));
}
__device__ __forceinline__ void split_bf16(float v, __nv_bfloat16& h, __nv_bfloat16& l) {
    h = __float2bfloat16(v);
    l = __float2bfloat16(v - __bfloat162float(h));
}

// ========== elementwise fp32 -> bf16 hi/lo ==========
__global__ void split_convert(const float* __restrict__ in,
                              __nv_bfloat16* __restrict__ hi,
                              __nv_bfloat16* __restrict__ lo, int n4) {
    int i = blockIdx.x * blockDim.x + threadIdx.x;
    if (i >= n4) return;
    float4 v = reinterpret_cast<const float4*>(in)[i];
    __nv_bfloat16 h0,l0,h1,l1,h2,l2,h3,l3;
    split_bf16(v.x, h0, l0); split_bf16(v.y, h1, l1);
    split_bf16(v.z, h2, l2); split_bf16(v.w, h3, l3);
    reinterpret_cast<__nv_bfloat162*>(hi)[i*2+0] = __nv_bfloat162(h0, h1);
    reinterpret_cast<__nv_bfloat162*>(hi)[i*2+1] = __nv_bfloat162(h2, h3);
    reinterpret_cast<__nv_bfloat162*>(lo)[i*2+0] = __nv_bfloat162(l0, l1);
    reinterpret_cast<__nv_bfloat162*>(lo)[i*2+1] = __nv_bfloat162(l2, l3);
}

// ========== transpose + split: W[K,N] -> Wt_hi/lo[N,K] ==========
__global__ void transpose_convert(const float* __restrict__ W,
                                  __nv_bfloat16* __restrict__ Th,
                                  __nv_bfloat16* __restrict__ Tl, int K, int N) {
    __shared__ float t[32][33];
    int n0 = blockIdx.x * 32, k0 = blockIdx.y * 32;
    int tx = threadIdx.x, ty = threadIdx.y;   // 32 x 8
    #pragma unroll
    for (int i = 0; i < 4; i++)
        t[ty + i*8][tx] = W[(size_t)(k0 + ty + i*8) * N + n0 + tx];
    __syncthreads();
    #pragma unroll
    for (int i = 0; i < 4; i++) {
        float v = t[tx][ty + i*8];
        __nv_bfloat16 h, l; split_bf16(v, h, l);
        size_t o = (size_t)(n0 + ty + i*8) * K + k0 + tx;
        Th[o] = h; Tl[o] = l;
    }
}

__global__ void pack_bias3(const float* __restrict__ a, const float* __restrict__ b,
                           const float* __restrict__ c, float* __restrict__ o) {
    int i = blockIdx.x * blockDim.x + threadIdx.x;
    if (i >= QKVN) return;
    o[i] = (i < DM) ? a[i] : (i < 2 * DM) ? b[i - DM] : c[i - 2 * DM];
}

// ========== HMMA GEMM: C[M,N] = A[M,K] @ Bt[N,K]^T + bias ==========
// 3xBF16 split, fp32 accumulate. CTA 128x128, 8 warps 32x64.
// K staged 64-wide, 3-stage cp.async pipeline.
#define STAGE_BYTES 65536
#define GEMM_SMEM (3 * STAGE_BYTES)
__global__ void __launch_bounds__(256, 1)
tc_gemm(const __nv_bfloat16* __restrict__ Ah, const __nv_bfloat16* __restrict__ Al,
        const __nv_bfloat16* __restrict__ Bh, const __nv_bfloat16* __restrict__ Bl,
        const float* __restrict__ bias,
        float* __restrict__ outF,
        __nv_bfloat16* __restrict__ outHi, __nv_bfloat16* __restrict__ outLo,
        int M, int N, int K, int act) {
    extern __shared__ char smem[];
    const uint32_t tiles = smem_to_u32(smem);
    const int tid = threadIdx.x;
    const int wid = tid >> 5;
    const int lane = tid & 31;
    const int warpM = wid >> 1;
    const int warpN = wid & 1;
    const int bm = blockIdx.y * 128;
    const int bn = blockIdx.x * 128;
    const int NB = K >> 6;

    const __nv_bfloat16* srcs[4] = {Ah, Al, Bh, Bl};

    auto stage = [&](int kb, int s) {
        #pragma unroll
        for (int t = 0; t < 4; t++) {
            const __nv_bfloat16* src = srcs[t];
            const int rbase = (t < 2) ? bm : bn;
            const uint32_t sb = tiles + (uint32_t)s * STAGE_BYTES + (uint32_t)t * 16384u;
            #pragma unroll
            for (int i = 0; i < 4; i++) {
                int chunk = tid + i * 256;
                int row = chunk >> 3;
                int c16 = chunk & 7;
                uint32_t off = (uint32_t)(row * 128 + c16 * 16);
                uint32_t dst = sb + SMEM_SWIZZLE_128B(off);
                const void* g = src + (size_t)(rbase + row) * K + kb * 64 + c16 * 8;
                asm volatile("cp.async.cg.shared.global [%0], [%1], 16;" :: "r"(dst), "l"(g));
            }
        }
        asm volatile("cp.async.commit_group;" ::: "memory");
    };

    float c[2][8][4] = {};

    stage(0, 0);
    if (NB > 1) stage(1, 1);

    const int lrow = lane & 15;
    const int lchunk = lane >> 4;

    for (int kb = 0; kb < NB; kb++) {
        const int s = kb % 3;
        if (kb + 1 < NB) asm volatile("cp.async.wait_group 1;" ::: "memory");
        else             asm volatile("cp.async.wait_group 0;" ::: "memory");
        __syncthreads();                 // tile kb ready; all warps done with slot (kb-1)%3
        if (kb + 2 < NB) stage(kb + 2, (kb + 2) % 3);

        const uint32_t base_s = tiles + (uint32_t)s * STAGE_BYTES;
        #pragma unroll
        for (int ks = 0; ks < 4; ks++) {
            uint32_t ah[2][4], al2[2][4];
            #pragma unroll
            for (int mt = 0; mt < 2; mt++) {
                uint32_t off = (uint32_t)((warpM * 32 + mt * 16 + lrow) * 128 + ks * 32 + lchunk * 16);
                uint32_t sw = SMEM_SWIZZLE_128B(off);
                ldsm_x4(ah[mt],  base_s + sw);
                ldsm_x4(al2[mt], base_s + 16384u + sw);
            }
            #pragma unroll
            for (int np = 0; np < 4; np++) {
                uint32_t off = (uint32_t)((warpN * 64 + np * 16 + lrow) * 128 + ks * 32 + lchunk * 16);
                uint32_t sw = SMEM_SWIZZLE_128B(off);
                uint32_t bh[4], bl[4];
                ldsm_x4(bh, base_s + 32768u + sw);
                ldsm_x4(bl, base_s + 49152u + sw);
                #pragma unroll
                for (int mt = 0; mt < 2; mt++) {
                    mma_bf16(c[mt][2*np],   ah[mt],  bh[0], bh[2]);
                    mma_bf16(c[mt][2*np+1], ah[mt],  bh[1], bh[3]);
                    mma_bf16(c[mt][2*np],   ah[mt],  bl[0], bl[2]);
                    mma_bf16(c[mt][2*np+1], ah[mt],  bl[1], bl[3]);
                    mma_bf16(c[mt][2*np],   al2[mt], bh[0], bh[2]);
                    mma_bf16(c[mt][2*np+1], al2[mt], bh[1], bh[3]);
                }
            }
        }
    }
    __syncthreads();

    // epilogue: regs -> smem (padded) -> coalesced global
    float* sD = reinterpret_cast<float*>(smem);   // 128 x 129
    #pragma unroll
    for (int mt = 0; mt < 2; mt++) {
        #pragma unroll
        for (int nt = 0; nt < 8; nt++) {
            int r0 = warpM * 32 + mt * 16 + (lane >> 2);
            int col = warpN * 64 + nt * 8 + (lane & 3) * 2;
            sD[r0 * 129 + col]           = c[mt][nt][0];
            sD[r0 * 129 + col + 1]       = c[mt][nt][1];
            sD[(r0 + 8) * 129 + col]     = c[mt][nt][2];
            sD[(r0 + 8) * 129 + col + 1] = c[mt][nt][3];
        }
    }
    __syncthreads();

    for (int idx = tid; idx < 128 * 128; idx += 256) {
        int r = idx >> 7, cc = idx & 127;
        float v = sD[r * 129 + cc] + bias[bn + cc];
        if (act) v = gelu_tanh(v);
        size_t go = (size_t)(bm + r) * N + bn + cc;
        if (outF) outF[go] = v;
        if (outHi) {
            __nv_bfloat16 h, l; split_bf16(v, h, l);
            outHi[go] = h; outLo[go] = l;
        }
    }
}

// ================= sliding-window attention, register-tiled =================
// block = (chunk, head, batch), 512 threads = 16 warps, 4 q-rows per warp.
// smem: sq[64][64], sk/sv/ss[192][66]; probs stored transposed (ss[j][i]),
// unnormalized; 1/sum folded into the output store.
#define KST 66
#define ATTN_SMEM ((64 * 64 + 3 * 192 * KST) * 4)
__global__ void __launch_bounds__(512, 1)
attn_kernel(const float* __restrict__ qkv, float* __restrict__ out) {
    extern __shared__ float sm[];
    float* sq = sm;                     // 64 x 64
    float* sk = sq + 64 * 64;           // 192 x 66
    float* sv = sk + 192 * KST;         // 192 x 66
    float* ss = sv + 192 * KST;         // 192 x 66  (probs^T)

    const int c = blockIdx.x, h = blockIdx.y, b = blockIdx.z;
    const int tid = threadIdx.x;
    const float scale = 0.125f;

    for (int idx = tid; idx < 64 * 64; idx += 512) {
        int i = idx >> 6, d = idx & 63;
        sq[idx] = qkv[((size_t)b * SS + c * 64 + i) * QKVN + h * HD + d] * scale;
    }
    for (int idx = tid; idx < 192 * 64; idx += 512) {
        int j = idx >> 6, d = idx & 63;
        int g = c * 64 - 64 + j;
        float kv = 0.f, vv = 0.f;
        if (g >= 0 && g < SS) {
            size_t off = ((size_t)b * SS + g) * QKVN + h * HD + d;
            kv = qkv[off + DM];
            vv = qkv[off + 2 * DM];
        }
        sk[j * KST + d] = kv;
        sv[j * KST + d] = vv;
    }
    __syncthreads();

    const int warp = tid >> 5, lane = tid & 31;
    const int i0 = warp * 4;

    // ---- QK^T: 4 rows x 6 cols per warp, float2 over d ----
    float acc[4][6] = {};
    #pragma unroll 4
    for (int dp = 0; dp < 32; dp++) {
        float2 kv[6];
        #pragma unroll
        for (int tt = 0; tt < 6; tt++)
            kv[tt] = *reinterpret_cast<const float2*>(&sk[(lane + 32 * tt) * KST + 2 * dp]);
        #pragma unroll
        for (int r = 0; r < 4; r++) {
            float2 q2 = *reinterpret_cast<const float2*>(&sq[(i0 + r) * 64 + 2 * dp]);
            #pragma unroll
            for (int tt = 0; tt < 6; tt++) {
                acc[r][tt] = fmaf(q2.x, kv[tt].x, acc[r][tt]);
                acc[r][tt] = fmaf(q2.y, kv[tt].y, acc[r][tt]);
            }
        }
    }

    // ---- mask + softmax (unnormalized), store probs^T ----
    float inv[4];
    #pragma unroll
    for (int r = 0; r < 4; r++) {
        int i = i0 + r;
        float m = -INFINITY;
        float s[6];
        #pragma unroll
        for (int tt = 0; tt < 6; tt++) {
            int j = lane + 32 * tt;
            int g = c * 64 - 64 + j;
            bool valid = (j >= i) && (j <= i + 2 * WIN) && (g >= 0) && (g < SS);
            s[tt] = valid ? acc[r][tt] : -INFINITY;
            m = fmaxf(m, s[tt]);
        }
        #pragma unroll
        for (int o = 16; o > 0; o >>= 1) m = fmaxf(m, __shfl_xor_sync(0xffffffffu, m, o));
        float sum = 0.f;
        #pragma unroll
        for (int tt = 0; tt < 6; tt++) {
            float e = __expf(s[tt] - m);
            ss[(lane + 32 * tt) * KST + i] = e;
            sum += e;
        }
        #pragma unroll
        for (int o = 16; o > 0; o >>= 1) sum += __shfl_xor_sync(0xffffffffu, sum, o);
        inv[r] = 1.0f / sum;
    }
    __syncwarp();

    // ---- PV: rows i0..i0+3, cols {lane, lane+32}; probs read as float2 row-pairs ----
    float o00 = 0.f, o01 = 0.f, o10 = 0.f, o11 = 0.f;
    float o20 = 0.f, o21 = 0.f, o30 = 0.f, o31 = 0.f;
    #pragma unroll 2
    for (int j = 0; j < 192; j++) {
        float v0 = sv[j * KST + lane];
        float v1 = sv[j * KST + lane + 32];
        float2 p01 = *reinterpret_cast<const float2*>(&ss[j * KST + i0]);
        float2 p23 = *reinterpret_cast<const float2*>(&ss[j * KST + i0 + 2]);
        o00 = fmaf(p01.x, v0, o00);  o01 = fmaf(p01.x, v1, o01);
        o10 = fmaf(p01.y, v0, o10);  o11 = fmaf(p01.y, v1, o11);
        o20 = fmaf(p23.x, v0, o20);  o21 = fmaf(p23.x, v1, o21);
        o30 = fmaf(p23.y, v0, o30);  o31 = fmaf(p23.y, v1, o31);
    }
    size_t ob = ((size_t)b * SS + c * 64 + i0) * DM + h * HD;
    out[ob + lane]               = o00 * inv[0];
    out[ob + lane + 32]          = o01 * inv[0];
    out[ob + DM + lane]          = o10 * inv[1];
    out[ob + DM + lane + 32]     = o11 * inv[1];
    out[ob + 2 * DM + lane]      = o20 * inv[2];
    out[ob + 2 * DM + lane + 32] = o21 * inv[2];
    out[ob + 3 * DM + lane]      = o30 * inv[3];
    out[ob + 3 * DM + lane + 32] = o31 * inv[3];
}

// ================= warp-per-row residual + LayerNorm =================
__global__ void __launch_bounds__(256)
add_ln_kernel(const float* __restrict__ a,
              const float* __restrict__ r,
              const float* __restrict__ g,
              const float* __restrict__ beta,
              float* __restrict__ out,
              __nv_bfloat16* __restrict__ outHi,
              __nv_bfloat16* __restrict__ outLo) {
    const int warp = threadIdx.x >> 5, lane = threadIdx.x & 31;
    const int row = blockIdx.x * 8 + warp;
    const float4* pa = reinterpret_cast<const float4*>(a + (size_t)row * DM);
    const float4* pr = reinterpret_cast<const float4*>(r + (size_t)row * DM);
    const float4* pg = reinterpret_cast<const float4*>(g);
    const float4* pb = reinterpret_cast<const float4*>(beta);

    float4 v[6];
    float sum = 0.f;
    #pragma unroll
    for (int ch = 0; ch < 6; ch++) {
        float4 va = pa[lane + 32 * ch];
        float4 vr = pr[lane + 32 * ch];
        v[ch] = make_float4(va.x + vr.x, va.y + vr.y, va.z + vr.z, va.w + vr.w);
        sum += v[ch].x + v[ch].y + v[ch].z + v[ch].w;
    }
    #pragma unroll
    for (int o = 16; o > 0; o >>= 1) sum += __shfl_xor_sync(0xffffffffu, sum, o);
    float mu = sum * (1.0f / DM);

    float var = 0.f;
    #pragma unroll
    for (int ch = 0; ch < 6; ch++) {
        float dx = v[ch].x - mu, dy = v[ch].y - mu, dz = v[ch].z - mu, dw = v[ch].w - mu;
        var += dx * dx + dy * dy + dz * dz + dw * dw;
    }
    #pragma unroll
    for (int o = 16; o > 0; o >>= 1) var += __shfl_xor_sync(0xffffffffu, var, o);
    float rstd = rsqrtf(var * (1.0f / DM) + 1e-5f);

    float4* po = reinterpret_cast<float4*>(out + (size_t)row * DM);
    #pragma unroll
    for (int ch = 0; ch < 6; ch++) {
        float4 gg = pg[lane + 32 * ch];
        float4 bb = pb[lane + 32 * ch];
        float4 y;
        y.x = (v[ch].x - mu) * rstd * gg.x + bb.x;
        y.y = (v[ch].y - mu) * rstd * gg.y + bb.y;
        y.z = (v[ch].z - mu) * rstd * gg.z + bb.z;
        y.w = (v[ch].w - mu) * rstd * gg.w + bb.w;
        po[lane + 32 * ch] = y;
        if (outHi) {
            size_t o4 = (size_t)row * DM + (lane + 32 * ch) * 4;
            __nv_bfloat16 h0,l0,h1,l1,h2,l2,h3,l3;
            split_bf16(y.x, h0, l0); split_bf16(y.y, h1, l1);
            split_bf16(y.z, h2, l2); split_bf16(y.w, h3, l3);
            reinterpret_cast<__nv_bfloat162*>(outHi + o4)[0] = __nv_bfloat162(h0, h1);
            reinterpret_cast<__nv_bfloat162*>(outHi + o4)[1] = __nv_bfloat162(h2, h3);
            reinterpret_cast<__nv_bfloat162*>(outLo + o4)[0] = __nv_bfloat162(l0, l1);
            reinterpret_cast<__nv_bfloat162*>(outLo + o4)[1] = __nv_bfloat162(l2, l3);
        }
    }
}

// ================= launch =================
extern "C" void kernel_launch(void* const* d_in, const int* in_sizes, int n_in,
                              void* d_out, int out_size) {
    const float* x     = (const float*)d_in[0];
    const float* Wq    = (const float*)d_in[1];
    const float* bq    = (const float*)d_in[2];
    const float* Wk    = (const float*)d_in[3];
    const float* bk    = (const float*)d_in[4];
    const float* Wv    = (const float*)d_in[5];
    const float* bv    = (const float*)d_in[6];
    const float* ln1_g = (const float*)d_in[7];
    const float* ln1_b = (const float*)d_in[8];
    const float* W1    = (const float*)d_in[9];
    const float* b1    = (const float*)d_in[10];
    const float* W2    = (const float*)d_in[11];
    const float* b2    = (const float*)d_in[12];
    const float* ln2_g = (const float*)d_in[13];
    const float* ln2_b = (const float*)d_in[14];
    float* out = (float*)d_out;

    float *qkv, *attn, *x1, *ff, *bqkv;
    __nv_bfloat16 *xh, *xl, *x1h, *x1l, *hidh, *hidl;
    __nv_bfloat16 *wqkvh, *wqkvl, *w1h, *w1l, *w2h, *w2l;
    cudaGetSymbolAddress((void**)&qkv, g_qkv);   cudaGetSymbolAddress((void**)&attn, g_attn);
    cudaGetSymbolAddress((void**)&x1, g_x1);     cudaGetSymbolAddress((void**)&ff, g_ff);
    cudaGetSymbolAddress((void**)&bqkv, g_bqkv);
    cudaGetSymbolAddress((void**)&xh, g_xh);     cudaGetSymbolAddress((void**)&xl, g_xl);
    cudaGetSymbolAddress((void**)&x1h, g_x1h);   cudaGetSymbolAddress((void**)&x1l, g_x1l);
    cudaGetSymbolAddress((void**)&hidh, g_hidh); cudaGetSymbolAddress((void**)&hidl, g_hidl);
    cudaGetSymbolAddress((void**)&wqkvh, g_wqkvh); cudaGetSymbolAddress((void**)&wqkvl, g_wqkvl);
    cudaGetSymbolAddress((void**)&w1h, g_w1h);   cudaGetSymbolAddress((void**)&w1l, g_w1l);
    cudaGetSymbolAddress((void**)&w2h, g_w2h);   cudaGetSymbolAddress((void**)&w2l, g_w2l);

    cudaFuncSetAttribute(tc_gemm, cudaFuncAttributeMaxDynamicSharedMemorySize, GEMM_SMEM);
    cudaFuncSetAttribute(attn_kernel, cudaFuncAttributeMaxDynamicSharedMemorySize, ATTN_SMEM);

    // ---- convert inputs ----
    {
        int n4 = MROWS * DM / 4;
        split_convert<<<(n4 + 255) / 256, 256>>>(x, xh, xl, n4);
        pack_bias3<<<(QKVN + 255) / 256, 256>>>(bq, bk, bv, bqkv);
        dim3 tb(32, 8);
        transpose_convert<<<dim3(DM / 32, DM / 32), tb>>>(Wq, wqkvh,               wqkvl,               DM, DM);
        transpose_convert<<<dim3(DM / 32, DM / 32), tb>>>(Wk, wqkvh + DM * DM,     wqkvl + DM * DM,     DM, DM);
        transpose_convert<<<dim3(DM / 32, DM / 32), tb>>>(Wv, wqkvh + 2 * DM * DM, wqkvl + 2 * DM * DM, DM, DM);
        transpose_convert<<<dim3(FF / 32, DM / 32), tb>>>(W1, w1h, w1l, DM, FF);
        transpose_convert<<<dim3(DM / 32, FF / 32), tb>>>(W2, w2h, w2l, FF, DM);
    }

    // ---- fused QKV projection: [8192,768] @ [768,2304] ----
    {
        dim3 grid(QKVN / 128, MROWS / 128);
        tc_gemm<<<grid, 256, GEMM_SMEM>>>(xh, xl, wqkvh, wqkvl, bqkv, qkv,
                                          nullptr, nullptr, MROWS, QKVN, DM, 0);
    }

    // ---- attention ----
    {
        dim3 grid(NC, NH, BB);
        attn_kernel<<<grid, 512, ATTN_SMEM>>>(qkv, attn);
    }

    // ---- x1 = LN(attn + x), emit bf16 hi/lo ----
    add_ln_kernel<<<MROWS / 8, 256>>>(attn, x, ln1_g, ln1_b, x1, x1h, x1l);

    // ---- FFN ----
    {
        dim3 grid1(FF / 128, MROWS / 128);
        tc_gemm<<<grid1, 256, GEMM_SMEM>>>(x1h, x1l, w1h, w1l, b1, nullptr,
                                           hidh, hidl, MROWS, FF, DM, 1);
        dim3 grid2(DM / 128, MROWS / 128);
        tc_gemm<<<grid2, 256, GEMM_SMEM>>>(hidh, hidl, w2h, w2l, b2, ff,
                                           nullptr, nullptr, MROWS, DM, FF, 0);
    }

    // ---- out = LN(ff + x1) ----
    add_ln_kernel<<<MROWS / 8, 256>>>(ff, x1, ln2_g, ln2_b, out, nullptr, nullptr);
}

// round 5
// speedup vs baseline: 3.5829x; 1.0008x over previous
#include <cuda_runtime.h>
#include <cuda_bf16.h>
#include <math.h>
#include <cstdint>

#define BB 2
#define SS 4096
#define DM 768
#define NH 12
#define FF 3072
#define WIN 64
#define HD 64
#define NC (SS / WIN)
#define MROWS (BB * SS)    // 8192
#define QKVN (3 * DM)      // 2304

// ================= helpers =================
__device__ __forceinline__ uint32_t smem_to_u32(const void* p) {
    uint32_t a;
    asm("{ .reg .u64 t; cvta.to.shared.u64 t, %1; cvt.u32.u64 %0, t; }" : "=r"(a) : "l"(p));
    return a;
}
#define SMEM_SWIZZLE_128B(o) ((o) ^ (((o) >> 3) & 0x70))

__device__ __forceinline__ void ldsm_x4(uint32_t r[4], uint32_t addr) {
    asm volatile("ldmatrix.sync.aligned.m8n8.x4.shared.b16 {%0,%1,%2,%3}, [%4];"
        : "=r"(r[0]), "=r"(r[1]), "=r"(r[2]), "=r"(r[3]) : "r"(addr));
}
__device__ __forceinline__ void mma_bf16(float c[4], const uint32_t a[4],
                                         uint32_t b0, uint32_t b1) {
    asm volatile("mma.sync.aligned.m16n8k16.row.col.f32.bf16.bf16.f32 "
        "{%0,%1,%2,%3}, {%4,%5,%6,%7}, {%8,%9}, {%0,%1,%2,%3};"
        : "+f"(c[0]), "+f"(c[1]), "+f"(c[2]), "+f"(c[3])
        : "r"(a[0]), "r"(a[1]), "r"(a[2]), "r"(a[3]), "r"(b0), "r"(b1));
}

// ================= scratch =================
__device__ float g_qkv[MROWS * QKVN];
__device__ float g_attn[MROWS * DM];
__device__ float g_x1[MROWS * DM];
__device__ float g_ff[MROWS * DM];
__device__ float g_bqkv[QKVN];
__device__ __nv_bfloat16 g_xh[MROWS * DM],  g_xl[MROWS * DM];
__device__ __nv_bfloat16 g_x1h[MROWS * DM], g_x1l[MROWS * DM];
__device__ __nv_bfloat16 g_hidh[MROWS * FF], g_hidl[MROWS * FF];
__device__ __nv_bfloat16 g_wqkvh[QKVN * DM], g_wqkvl[QKVN * DM];
__device__ __nv_bfloat16 g_w1h[FF * DM], g_w1l[FF * DM];
__device__ __nv_bfloat16 g_w2h[DM * FF], g_w2l[DM * FF];

__device__ __forceinline__ float gelu_tanh(float x) {
    const float c = 0.7978845608028654f;
    float x3 = x * x * x;
    return 0.5f * x * (1.0f + tanhf(c * (x + 0.044715f * x3)));
}
__device__ __forceinline__ void split_bf16(float v, __nv_bfloat16& h, __nv_bfloat16& l) {
    h = __float2bfloat16(v);
    l = __float2bfloat16(v - __bfloat162float(h));
}

// ========== elementwise fp32 -> bf16 hi/lo ==========
__global__ void split_convert(const float* __restrict__ in,
                              __nv_bfloat16* __restrict__ hi,
                              __nv_bfloat16* __restrict__ lo, int n4) {
    int i = blockIdx.x * blockDim.x + threadIdx.x;
    if (i >= n4) return;
    float4 v = reinterpret_cast<const float4*>(in)[i];
    __nv_bfloat16 h0,l0,h1,l1,h2,l2,h3,l3;
    split_bf16(v.x, h0, l0); split_bf16(v.y, h1, l1);
    split_bf16(v.z, h2, l2); split_bf16(v.w, h3, l3);
    reinterpret_cast<__nv_bfloat162*>(hi)[i*2+0] = __nv_bfloat162(h0, h1);
    reinterpret_cast<__nv_bfloat162*>(hi)[i*2+1] = __nv_bfloat162(h2, h3);
    reinterpret_cast<__nv_bfloat162*>(lo)[i*2+0] = __nv_bfloat162(l0, l1);
    reinterpret_cast<__nv_bfloat162*>(lo)[i*2+1] = __nv_bfloat162(l2, l3);
}

// ========== transpose + split: W[K,N] -> Wt_hi/lo[N,K] ==========
__global__ void transpose_convert(const float* __restrict__ W,
                                  __nv_bfloat16* __restrict__ Th,
                                  __nv_bfloat16* __restrict__ Tl, int K, int N) {
    __shared__ float t[32][33];
    int n0 = blockIdx.x * 32, k0 = blockIdx.y * 32;
    int tx = threadIdx.x, ty = threadIdx.y;   // 32 x 8
    #pragma unroll
    for (int i = 0; i < 4; i++)
        t[ty + i*8][tx] = W[(size_t)(k0 + ty + i*8) * N + n0 + tx];
    __syncthreads();
    #pragma unroll
    for (int i = 0; i < 4; i++) {
        float v = t[tx][ty + i*8];
        __nv_bfloat16 h, l; split_bf16(v, h, l);
        size_t o = (size_t)(n0 + ty + i*8) * K + k0 + tx;
        Th[o] = h; Tl[o] = l;
    }
}

__global__ void pack_bias3(const float* __restrict__ a, const float* __restrict__ b,
                           const float* __restrict__ c, float* __restrict__ o) {
    int i = blockIdx.x * blockDim.x + threadIdx.x;
    if (i >= QKVN) return;
    o[i] = (i < DM) ? a[i] : (i < 2 * DM) ? b[i - DM] : c[i - 2 * DM];
}

// ========== HMMA GEMM: C[M,N] = A[M,K] @ Bt[N,K]^T + bias ==========
// 3xBF16 split, fp32 accumulate. CTA 128x128, 8 warps 32x64.
// K staged 64-wide, 3-stage cp.async pipeline.
#define STAGE_BYTES 65536
#define GEMM_SMEM (3 * STAGE_BYTES)
__global__ void __launch_bounds__(256, 1)
tc_gemm(const __nv_bfloat16* __restrict__ Ah, const __nv_bfloat16* __restrict__ Al,
        const __nv_bfloat16* __restrict__ Bh, const __nv_bfloat16* __restrict__ Bl,
        const float* __restrict__ bias,
        float* __restrict__ outF,
        __nv_bfloat16* __restrict__ outHi, __nv_bfloat16* __restrict__ outLo,
        int M, int N, int K, int act) {
    extern __shared__ char smem[];
    const uint32_t tiles = smem_to_u32(smem);
    const int tid = threadIdx.x;
    const int wid = tid >> 5;
    const int lane = tid & 31;
    const int warpM = wid >> 1;
    const int warpN = wid & 1;
    const int bm = blockIdx.y * 128;
    const int bn = blockIdx.x * 128;
    const int NB = K >> 6;

    const __nv_bfloat16* srcs[4] = {Ah, Al, Bh, Bl};

    auto stage = [&](int kb, int s) {
        #pragma unroll
        for (int t = 0; t < 4; t++) {
            const __nv_bfloat16* src = srcs[t];
            const int rbase = (t < 2) ? bm : bn;
            const uint32_t sb = tiles + (uint32_t)s * STAGE_BYTES + (uint32_t)t * 16384u;
            #pragma unroll
            for (int i = 0; i < 4; i++) {
                int chunk = tid + i * 256;
                int row = chunk >> 3;
                int c16 = chunk & 7;
                uint32_t off = (uint32_t)(row * 128 + c16 * 16);
                uint32_t dst = sb + SMEM_SWIZZLE_128B(off);
                const void* g = src + (size_t)(rbase + row) * K + kb * 64 + c16 * 8;
                asm volatile("cp.async.cg.shared.global [%0], [%1], 16;" :: "r"(dst), "l"(g));
            }
        }
        asm volatile("cp.async.commit_group;" ::: "memory");
    };

    float c[2][8][4] = {};

    stage(0, 0);
    if (NB > 1) stage(1, 1);

    const int lrow = lane & 15;
    const int lchunk = lane >> 4;

    for (int kb = 0; kb < NB; kb++) {
        const int s = kb % 3;
        if (kb + 1 < NB) asm volatile("cp.async.wait_group 1;" ::: "memory");
        else             asm volatile("cp.async.wait_group 0;" ::: "memory");
        __syncthreads();                 // tile kb ready; all warps done with slot (kb-1)%3
        if (kb + 2 < NB) stage(kb + 2, (kb + 2) % 3);

        const uint32_t base_s = tiles + (uint32_t)s * STAGE_BYTES;
        #pragma unroll
        for (int ks = 0; ks < 4; ks++) {
            uint32_t ah[2][4], al2[2][4];
            #pragma unroll
            for (int mt = 0; mt < 2; mt++) {
                uint32_t off = (uint32_t)((warpM * 32 + mt * 16 + lrow) * 128 + ks * 32 + lchunk * 16);
                uint32_t sw = SMEM_SWIZZLE_128B(off);
                ldsm_x4(ah[mt],  base_s + sw);
                ldsm_x4(al2[mt], base_s + 16384u + sw);
            }
            #pragma unroll
            for (int np = 0; np < 4; np++) {
                uint32_t off = (uint32_t)((warpN * 64 + np * 16 + lrow) * 128 + ks * 32 + lchunk * 16);
                uint32_t sw = SMEM_SWIZZLE_128B(off);
                uint32_t bh[4], bl[4];
                ldsm_x4(bh, base_s + 32768u + sw);
                ldsm_x4(bl, base_s + 49152u + sw);
                #pragma unroll
                for (int mt = 0; mt < 2; mt++) {
                    mma_bf16(c[mt][2*np],   ah[mt],  bh[0], bh[2]);
                    mma_bf16(c[mt][2*np+1], ah[mt],  bh[1], bh[3]);
                    mma_bf16(c[mt][2*np],   ah[mt],  bl[0], bl[2]);
                    mma_bf16(c[mt][2*np+1], ah[mt],  bl[1], bl[3]);
                    mma_bf16(c[mt][2*np],   al2[mt], bh[0], bh[2]);
                    mma_bf16(c[mt][2*np+1], al2[mt], bh[1], bh[3]);
                }
            }
        }
    }
    __syncthreads();

    // epilogue: regs -> smem (padded) -> coalesced global
    float* sD = reinterpret_cast<float*>(smem);   // 128 x 129
    #pragma unroll
    for (int mt = 0; mt < 2; mt++) {
        #pragma unroll
        for (int nt = 0; nt < 8; nt++) {
            int r0 = warpM * 32 + mt * 16 + (lane >> 2);
            int col = warpN * 64 + nt * 8 + (lane & 3) * 2;
            sD[r0 * 129 + col]           = c[mt][nt][0];
            sD[r0 * 129 + col + 1]       = c[mt][nt][1];
            sD[(r0 + 8) * 129 + col]     = c[mt][nt][2];
            sD[(r0 + 8) * 129 + col + 1] = c[mt][nt][3];
        }
    }
    __syncthreads();

    for (int idx = tid; idx < 128 * 128; idx += 256) {
        int r = idx >> 7, cc = idx & 127;
        float v = sD[r * 129 + cc] + bias[bn + cc];
        if (act) v = gelu_tanh(v);
        size_t go = (size_t)(bm + r) * N + bn + cc;
        if (outF) outF[go] = v;
        if (outHi) {
            __nv_bfloat16 h, l; split_bf16(v, h, l);
            outHi[go] = h; outLo[go] = l;
        }
    }
}

// ================= sliding-window attention, register-tiled =================
// block = (chunk, head, batch), 512 threads = 16 warps, 4 q-rows per warp.
// smem: sq[64][64], sk/sv/ss[192][66]; probs stored transposed (ss[j][i]),
// unnormalized; 1/sum folded into the output store.
#define KST 66
#define ATTN_SMEM ((64 * 64 + 3 * 192 * KST) * 4)
__global__ void __launch_bounds__(512, 1)
attn_kernel(const float* __restrict__ qkv, float* __restrict__ out) {
    extern __shared__ float sm[];
    float* sq = sm;                     // 64 x 64
    float* sk = sq + 64 * 64;           // 192 x 66
    float* sv = sk + 192 * KST;         // 192 x 66
    float* ss = sv + 192 * KST;         // 192 x 66  (probs^T)

    const int c = blockIdx.x, h = blockIdx.y, b = blockIdx.z;
    const int tid = threadIdx.x;
    const float scale = 0.125f;

    for (int idx = tid; idx < 64 * 64; idx += 512) {
        int i = idx >> 6, d = idx & 63;
        sq[idx] = qkv[((size_t)b * SS + c * 64 + i) * QKVN + h * HD + d] * scale;
    }
    for (int idx = tid; idx < 192 * 64; idx += 512) {
        int j = idx >> 6, d = idx & 63;
        int g = c * 64 - 64 + j;
        float kv = 0.f, vv = 0.f;
        if (g >= 0 && g < SS) {
            size_t off = ((size_t)b * SS + g) * QKVN + h * HD + d;
            kv = qkv[off + DM];
            vv = qkv[off + 2 * DM];
        }
        sk[j * KST + d] = kv;
        sv[j * KST + d] = vv;
    }
    __syncthreads();

    const int warp = tid >> 5, lane = tid & 31;
    const int i0 = warp * 4;

    // ---- QK^T: 4 rows x 6 cols per warp, float2 over d ----
    float acc[4][6] = {};
    #pragma unroll 4
    for (int dp = 0; dp < 32; dp++) {
        float2 kv[6];
        #pragma unroll
        for (int tt = 0; tt < 6; tt++)
            kv[tt] = *reinterpret_cast<const float2*>(&sk[(lane + 32 * tt) * KST + 2 * dp]);
        #pragma unroll
        for (int r = 0; r < 4; r++) {
            float2 q2 = *reinterpret_cast<const float2*>(&sq[(i0 + r) * 64 + 2 * dp]);
            #pragma unroll
            for (int tt = 0; tt < 6; tt++) {
                acc[r][tt] = fmaf(q2.x, kv[tt].x, acc[r][tt]);
                acc[r][tt] = fmaf(q2.y, kv[tt].y, acc[r][tt]);
            }
        }
    }

    // ---- mask + softmax (unnormalized), store probs^T ----
    float inv[4];
    #pragma unroll
    for (int r = 0; r < 4; r++) {
        int i = i0 + r;
        float m = -INFINITY;
        float s[6];
        #pragma unroll
        for (int tt = 0; tt < 6; tt++) {
            int j = lane + 32 * tt;
            int g = c * 64 - 64 + j;
            bool valid = (j >= i) && (j <= i + 2 * WIN) && (g >= 0) && (g < SS);
            s[tt] = valid ? acc[r][tt] : -INFINITY;
            m = fmaxf(m, s[tt]);
        }
        #pragma unroll
        for (int o = 16; o > 0; o >>= 1) m = fmaxf(m, __shfl_xor_sync(0xffffffffu, m, o));
        float sum = 0.f;
        #pragma unroll
        for (int tt = 0; tt < 6; tt++) {
            float e = __expf(s[tt] - m);
            ss[(lane + 32 * tt) * KST + i] = e;
            sum += e;
        }
        #pragma unroll
        for (int o = 16; o > 0; o >>= 1) sum += __shfl_xor_sync(0xffffffffu, sum, o);
        inv[r] = 1.0f / sum;
    }
    __syncwarp();

    // ---- PV: rows i0..i0+3, cols {lane, lane+32}; probs read as float2 row-pairs ----
    float o00 = 0.f, o01 = 0.f, o10 = 0.f, o11 = 0.f;
    float o20 = 0.f, o21 = 0.f, o30 = 0.f, o31 = 0.f;
    #pragma unroll 2
    for (int j = 0; j < 192; j++) {
        float v0 = sv[j * KST + lane];
        float v1 = sv[j * KST + lane + 32];
        float2 p01 = *reinterpret_cast<const float2*>(&ss[j * KST + i0]);
        float2 p23 = *reinterpret_cast<const float2*>(&ss[j * KST + i0 + 2]);
        o00 = fmaf(p01.x, v0, o00);  o01 = fmaf(p01.x, v1, o01);
        o10 = fmaf(p01.y, v0, o10);  o11 = fmaf(p01.y, v1, o11);
        o20 = fmaf(p23.x, v0, o20);  o21 = fmaf(p23.x, v1, o21);
        o30 = fmaf(p23.y, v0, o30);  o31 = fmaf(p23.y, v1, o31);
    }
    size_t ob = ((size_t)b * SS + c * 64 + i0) * DM + h * HD;
    out[ob + lane]               = o00 * inv[0];
    out[ob + lane + 32]          = o01 * inv[0];
    out[ob + DM + lane]          = o10 * inv[1];
    out[ob + DM + lane + 32]     = o11 * inv[1];
    out[ob + 2 * DM + lane]      = o20 * inv[2];
    out[ob + 2 * DM + lane + 32] = o21 * inv[2];
    out[ob + 3 * DM + lane]      = o30 * inv[3];
    out[ob + 3 * DM + lane + 32] = o31 * inv[3];
}

// ================= warp-per-row residual + LayerNorm =================
__global__ void __launch_bounds__(256)
add_ln_kernel(const float* __restrict__ a,
              const float* __restrict__ r,
              const float* __restrict__ g,
              const float* __restrict__ beta,
              float* __restrict__ out,
              __nv_bfloat16* __restrict__ outHi,
              __nv_bfloat16* __restrict__ outLo) {
    const int warp = threadIdx.x >> 5, lane = threadIdx.x & 31;
    const int row = blockIdx.x * 8 + warp;
    const float4* pa = reinterpret_cast<const float4*>(a + (size_t)row * DM);
    const float4* pr = reinterpret_cast<const float4*>(r + (size_t)row * DM);
    const float4* pg = reinterpret_cast<const float4*>(g);
    const float4* pb = reinterpret_cast<const float4*>(beta);

    float4 v[6];
    float sum = 0.f;
    #pragma unroll
    for (int ch = 0; ch < 6; ch++) {
        float4 va = pa[lane + 32 * ch];
        float4 vr = pr[lane + 32 * ch];
        v[ch] = make_float4(va.x + vr.x, va.y + vr.y, va.z + vr.z, va.w + vr.w);
        sum += v[ch].x + v[ch].y + v[ch].z + v[ch].w;
    }
    #pragma unroll
    for (int o = 16; o > 0; o >>= 1) sum += __shfl_xor_sync(0xffffffffu, sum, o);
    float mu = sum * (1.0f / DM);

    float var = 0.f;
    #pragma unroll
    for (int ch = 0; ch < 6; ch++) {
        float dx = v[ch].x - mu, dy = v[ch].y - mu, dz = v[ch].z - mu, dw = v[ch].w - mu;
        var += dx * dx + dy * dy + dz * dz + dw * dw;
    }
    #pragma unroll
    for (int o = 16; o > 0; o >>= 1) var += __shfl_xor_sync(0xffffffffu, var, o);
    float rstd = rsqrtf(var * (1.0f / DM) + 1e-5f);

    float4* po = reinterpret_cast<float4*>(out + (size_t)row * DM);
    #pragma unroll
    for (int ch = 0; ch < 6; ch++) {
        float4 gg = pg[lane + 32 * ch];
        float4 bb = pb[lane + 32 * ch];
        float4 y;
        y.x = (v[ch].x - mu) * rstd * gg.x + bb.x;
        y.y = (v[ch].y - mu) * rstd * gg.y + bb.y;
        y.z = (v[ch].z - mu) * rstd * gg.z + bb.z;
        y.w = (v[ch].w - mu) * rstd * gg.w + bb.w;
        po[lane + 32 * ch] = y;
        if (outHi) {
            size_t o4 = (size_t)row * DM + (lane + 32 * ch) * 4;
            __nv_bfloat16 h0,l0,h1,l1,h2,l2,h3,l3;
            split_bf16(y.x, h0, l0); split_bf16(y.y, h1, l1);
            split_bf16(y.z, h2, l2); split_bf16(y.w, h3, l3);
            reinterpret_cast<__nv_bfloat162*>(outHi + o4)[0] = __nv_bfloat162(h0, h1);
            reinterpret_cast<__nv_bfloat162*>(outHi + o4)[1] = __nv_bfloat162(h2, h3);
            reinterpret_cast<__nv_bfloat162*>(outLo + o4)[0] = __nv_bfloat162(l0, l1);
            reinterpret_cast<__nv_bfloat162*>(outLo + o4)[1] = __nv_bfloat162(l2, l3);
        }
    }
}

// ================= launch =================
extern "C" void kernel_launch(void* const* d_in, const int* in_sizes, int n_in,
                              void* d_out, int out_size) {
    const float* x     = (const float*)d_in[0];
    const float* Wq    = (const float*)d_in[1];
    const float* bq    = (const float*)d_in[2];
    const float* Wk    = (const float*)d_in[3];
    const float* bk    = (const float*)d_in[4];
    const float* Wv    = (const float*)d_in[5];
    const float* bv    = (const float*)d_in[6];
    const float* ln1_g = (const float*)d_in[7];
    const float* ln1_b = (const float*)d_in[8];
    const float* W1    = (const float*)d_in[9];
    const float* b1    = (const float*)d_in[10];
    const float* W2    = (const float*)d_in[11];
    const float* b2    = (const float*)d_in[12];
    const float* ln2_g = (const float*)d_in[13];
    const float* ln2_b = (const float*)d_in[14];
    float* out = (float*)d_out;

    float *qkv, *attn, *x1, *ff, *bqkv;
    __nv_bfloat16 *xh, *xl, *x1h, *x1l, *hidh, *hidl;
    __nv_bfloat16 *wqkvh, *wqkvl, *w1h, *w1l, *w2h, *w2l;
    cudaGetSymbolAddress((void**)&qkv, g_qkv);   cudaGetSymbolAddress((void**)&attn, g_attn);
    cudaGetSymbolAddress((void**)&x1, g_x1);     cudaGetSymbolAddress((void**)&ff, g_ff);
    cudaGetSymbolAddress((void**)&bqkv, g_bqkv);
    cudaGetSymbolAddress((void**)&xh, g_xh);     cudaGetSymbolAddress((void**)&xl, g_xl);
    cudaGetSymbolAddress((void**)&x1h, g_x1h);   cudaGetSymbolAddress((void**)&x1l, g_x1l);
    cudaGetSymbolAddress((void**)&hidh, g_hidh); cudaGetSymbolAddress((void**)&hidl, g_hidl);
    cudaGetSymbolAddress((void**)&wqkvh, g_wqkvh); cudaGetSymbolAddress((void**)&wqkvl, g_wqkvl);
    cudaGetSymbolAddress((void**)&w1h, g_w1h);   cudaGetSymbolAddress((void**)&w1l, g_w1l);
    cudaGetSymbolAddress((void**)&w2h, g_w2h);   cudaGetSymbolAddress((void**)&w2l, g_w2l);

    cudaFuncSetAttribute(tc_gemm, cudaFuncAttributeMaxDynamicSharedMemorySize, GEMM_SMEM);
    cudaFuncSetAttribute(attn_kernel, cudaFuncAttributeMaxDynamicSharedMemorySize, ATTN_SMEM);

    // ---- convert inputs ----
    {
        int n4 = MROWS * DM / 4;
        split_convert<<<(n4 + 255) / 256, 256>>>(x, xh, xl, n4);
        pack_bias3<<<(QKVN + 255) / 256, 256>>>(bq, bk, bv, bqkv);
        dim3 tb(32, 8);
        transpose_convert<<<dim3(DM / 32, DM / 32), tb>>>(Wq, wqkvh,               wqkvl,               DM, DM);
        transpose_convert<<<dim3(DM / 32, DM / 32), tb>>>(Wk, wqkvh + DM * DM,     wqkvl + DM * DM,     DM, DM);
        transpose_convert<<<dim3(DM / 32, DM / 32), tb>>>(Wv, wqkvh + 2 * DM * DM, wqkvl + 2 * DM * DM, DM, DM);
        transpose_convert<<<dim3(FF / 32, DM / 32), tb>>>(W1, w1h, w1l, DM, FF);
        transpose_convert<<<dim3(DM / 32, FF / 32), tb>>>(W2, w2h, w2l, FF, DM);
    }

    // ---- fused QKV projection: [8192,768] @ [768,2304] ----
    {
        dim3 grid(QKVN / 128, MROWS / 128);
        tc_gemm<<<grid, 256, GEMM_SMEM>>>(xh, xl, wqkvh, wqkvl, bqkv, qkv,
                                          nullptr, nullptr, MROWS, QKVN, DM, 0);
    }

    // ---- attention ----
    {
        dim3 grid(NC, NH, BB);
        attn_kernel<<<grid, 512, ATTN_SMEM>>>(qkv, attn);
    }

    // ---- x1 = LN(attn + x), emit bf16 hi/lo ----
    add_ln_kernel<<<MROWS / 8, 256>>>(attn, x, ln1_g, ln1_b, x1, x1h, x1l);

    // ---- FFN ----
    {
        dim3 grid1(FF / 128, MROWS / 128);
        tc_gemm<<<grid1, 256, GEMM_SMEM>>>(x1h, x1l, w1h, w1l, b1, nullptr,
                                           hidh, hidl, MROWS, FF, DM, 1);
        dim3 grid2(DM / 128, MROWS / 128);
        tc_gemm<<<grid2, 256, GEMM_SMEM>>>(hidh, hidl, w2h, w2l, b2, ff,
                                           nullptr, nullptr, MROWS, DM, FF, 0);
    }

    // ---- out = LN(ff + x1) ----
    add_ln_kernel<<<MROWS / 8, 256>>>(ff, x1, ln2_g, ln2_b, out, nullptr, nullptr);
}

// round 6
// speedup vs baseline: 3.9632x; 1.1061x over previous
#include <cuda_runtime.h>
#include <cuda_bf16.h>
#include <math.h>
#include <cstdint>

#define BB 2
#define SS 4096
#define DM 768
#define NH 12
#define FF 3072
#define WIN 64
#define HD 64
#define NC (SS / WIN)
#define MROWS (BB * SS)    // 8192
#define QKVN (3 * DM)      // 2304
#define KVW (2 * DM)       // 1536 packed k|v width

// ================= helpers =================
__device__ __forceinline__ uint32_t smem_to_u32(const void* p) {
    uint32_t a;
    asm("{ .reg .u64 t; cvta.to.shared.u64 t, %1; cvt.u32.u64 %0, t; }" : "=r"(a) : "l"(p));
    return a;
}
#define SMEM_SWIZZLE_128B(o) ((o) ^ (((o) >> 3) & 0x70))

__device__ __forceinline__ void ldsm_x4(uint32_t r[4], uint32_t addr) {
    asm volatile("ldmatrix.sync.aligned.m8n8.x4.shared.b16 {%0,%1,%2,%3}, [%4];"
        : "=r"(r[0]), "=r"(r[1]), "=r"(r[2]), "=r"(r[3]) : "r"(addr));
}
__device__ __forceinline__ void ldsm_x4_trans(uint32_t r[4], uint32_t addr) {
    asm volatile("ldmatrix.sync.aligned.m8n8.x4.trans.shared.b16 {%0,%1,%2,%3}, [%4];"
        : "=r"(r[0]), "=r"(r[1]), "=r"(r[2]), "=r"(r[3]) : "r"(addr));
}
__device__ __forceinline__ void mma_bf16(float c[4], const uint32_t a[4],
                                         uint32_t b0, uint32_t b1) {
    asm volatile("mma.sync.aligned.m16n8k16.row.col.f32.bf16.bf16.f32 "
        "{%0,%1,%2,%3}, {%4,%5,%6,%7}, {%8,%9}, {%0,%1,%2,%3};"
        : "+f"(c[0]), "+f"(c[1]), "+f"(c[2]), "+f"(c[3])
        : "r"(a[0]), "r"(a[1]), "r"(a[2]), "r"(a[3]), "r"(b0), "r"(b1));
}
__device__ __forceinline__ void split_bf16(float v, __nv_bfloat16& h, __nv_bfloat16& l) {
    h = __float2bfloat16(v);
    l = __float2bfloat16(v - __bfloat162float(h));
}
__device__ __forceinline__ uint32_t pack_hi(float x, float y) {
    __nv_bfloat162 t(__float2bfloat16(x), __float2bfloat16(y));
    return *reinterpret_cast<uint32_t*>(&t);
}
__device__ __forceinline__ uint32_t pack_lo(float x, float y) {
    __nv_bfloat16 hx = __float2bfloat16(x), hy = __float2bfloat16(y);
    __nv_bfloat162 t(__float2bfloat16(x - __bfloat162float(hx)),
                     __float2bfloat16(y - __bfloat162float(hy)));
    return *reinterpret_cast<uint32_t*>(&t);
}
__device__ __forceinline__ float gelu_tanh(float x) {
    const float c = 0.7978845608028654f;
    float x3 = x * x * x;
    return 0.5f * x * (1.0f + tanhf(c * (x + 0.044715f * x3)));
}

// ================= scratch =================
__device__ float g_qf[MROWS * DM];
__device__ float g_attn[MROWS * DM];
__device__ float g_x1[MROWS * DM];
__device__ float g_ff[MROWS * DM];
__device__ float g_bqkv[QKVN];
__device__ __nv_bfloat16 g_kvh[MROWS * KVW], g_kvl[MROWS * KVW];
__device__ __nv_bfloat16 g_xh[MROWS * DM],  g_xl[MROWS * DM];
__device__ __nv_bfloat16 g_x1h[MROWS * DM], g_x1l[MROWS * DM];
__device__ __nv_bfloat16 g_hidh[MROWS * FF], g_hidl[MROWS * FF];
__device__ __nv_bfloat16 g_wqkvh[QKVN * DM], g_wqkvl[QKVN * DM];
__device__ __nv_bfloat16 g_w1h[FF * DM], g_w1l[FF * DM];
__device__ __nv_bfloat16 g_w2h[DM * FF], g_w2l[DM * FF];

// ========== elementwise fp32 -> bf16 hi/lo ==========
__global__ void split_convert(const float* __restrict__ in,
                              __nv_bfloat16* __restrict__ hi,
                              __nv_bfloat16* __restrict__ lo, int n4) {
    int i = blockIdx.x * blockDim.x + threadIdx.x;
    if (i >= n4) return;
    float4 v = reinterpret_cast<const float4*>(in)[i];
    __nv_bfloat16 h0,l0,h1,l1,h2,l2,h3,l3;
    split_bf16(v.x, h0, l0); split_bf16(v.y, h1, l1);
    split_bf16(v.z, h2, l2); split_bf16(v.w, h3, l3);
    reinterpret_cast<__nv_bfloat162*>(hi)[i*2+0] = __nv_bfloat162(h0, h1);
    reinterpret_cast<__nv_bfloat162*>(hi)[i*2+1] = __nv_bfloat162(h2, h3);
    reinterpret_cast<__nv_bfloat162*>(lo)[i*2+0] = __nv_bfloat162(l0, l1);
    reinterpret_cast<__nv_bfloat162*>(lo)[i*2+1] = __nv_bfloat162(l2, l3);
}

// ========== transpose + split: W[K,N] -> Wt_hi/lo[N,K] ==========
__global__ void transpose_convert(const float* __restrict__ W,
                                  __nv_bfloat16* __restrict__ Th,
                                  __nv_bfloat16* __restrict__ Tl, int K, int N) {
    __shared__ float t[32][33];
    int n0 = blockIdx.x * 32, k0 = blockIdx.y * 32;
    int tx = threadIdx.x, ty = threadIdx.y;   // 32 x 8
    #pragma unroll
    for (int i = 0; i < 4; i++)
        t[ty + i*8][tx] = W[(size_t)(k0 + ty + i*8) * N + n0 + tx];
    __syncthreads();
    #pragma unroll
    for (int i = 0; i < 4; i++) {
        float v = t[tx][ty + i*8];
        __nv_bfloat16 h, l; split_bf16(v, h, l);
        size_t o = (size_t)(n0 + ty + i*8) * K + k0 + tx;
        Th[o] = h; Tl[o] = l;
    }
}

__global__ void pack_bias3(const float* __restrict__ a, const float* __restrict__ b,
                           const float* __restrict__ c, float* __restrict__ o) {
    int i = blockIdx.x * blockDim.x + threadIdx.x;
    if (i >= QKVN) return;
    o[i] = (i < DM) ? a[i] : (i < 2 * DM) ? b[i - DM] : c[i - 2 * DM];
}

// ========== HMMA GEMM: C[M,N] = A[M,K] @ Bt[N,K]^T + bias ==========
// 3xBF16 split, fp32 accumulate. CTA 128x128, 8 warps 32x64, 3-stage cp.async.
// mode 0: fp32 out (stride N). mode 1: gelu + hi/lo out (stride N).
// mode 2 (QKV): global col < DM -> fp32*0.125 to outF (stride DM);
//               else hi/lo to outHi/Lo at col-DM (stride KVW).
#define STAGE_BYTES 65536
#define GEMM_SMEM (3 * STAGE_BYTES)
__global__ void __launch_bounds__(256, 1)
tc_gemm(const __nv_bfloat16* __restrict__ Ah, const __nv_bfloat16* __restrict__ Al,
        const __nv_bfloat16* __restrict__ Bh, const __nv_bfloat16* __restrict__ Bl,
        const float* __restrict__ bias,
        float* __restrict__ outF,
        __nv_bfloat16* __restrict__ outHi, __nv_bfloat16* __restrict__ outLo,
        int M, int N, int K, int mode) {
    extern __shared__ char smem[];
    const uint32_t tiles = smem_to_u32(smem);
    const int tid = threadIdx.x;
    const int wid = tid >> 5;
    const int lane = tid & 31;
    const int warpM = wid >> 1;
    const int warpN = wid & 1;
    const int bm = blockIdx.y * 128;
    const int bn = blockIdx.x * 128;
    const int NB = K >> 6;

    const __nv_bfloat16* srcs[4] = {Ah, Al, Bh, Bl};

    auto stage = [&](int kb, int s) {
        #pragma unroll
        for (int t = 0; t < 4; t++) {
            const __nv_bfloat16* src = srcs[t];
            const int rbase = (t < 2) ? bm : bn;
            const uint32_t sb = tiles + (uint32_t)s * STAGE_BYTES + (uint32_t)t * 16384u;
            #pragma unroll
            for (int i = 0; i < 4; i++) {
                int chunk = tid + i * 256;
                int row = chunk >> 3;
                int c16 = chunk & 7;
                uint32_t off = (uint32_t)(row * 128 + c16 * 16);
                uint32_t dst = sb + SMEM_SWIZZLE_128B(off);
                const void* g = src + (size_t)(rbase + row) * K + kb * 64 + c16 * 8;
                asm volatile("cp.async.cg.shared.global [%0], [%1], 16;" :: "r"(dst), "l"(g));
            }
        }
        asm volatile("cp.async.commit_group;" ::: "memory");
    };

    float c[2][8][4] = {};

    stage(0, 0);
    if (NB > 1) stage(1, 1);

    const int lrow = lane & 15;
    const int lchunk = lane >> 4;

    for (int kb = 0; kb < NB; kb++) {
        const int s = kb % 3;
        if (kb + 1 < NB) asm volatile("cp.async.wait_group 1;" ::: "memory");
        else             asm volatile("cp.async.wait_group 0;" ::: "memory");
        __syncthreads();
        if (kb + 2 < NB) stage(kb + 2, (kb + 2) % 3);

        const uint32_t base_s = tiles + (uint32_t)s * STAGE_BYTES;
        #pragma unroll
        for (int ks = 0; ks < 4; ks++) {
            uint32_t ah[2][4], al2[2][4];
            #pragma unroll
            for (int mt = 0; mt < 2; mt++) {
                uint32_t off = (uint32_t)((warpM * 32 + mt * 16 + lrow) * 128 + ks * 32 + lchunk * 16);
                uint32_t sw = SMEM_SWIZZLE_128B(off);
                ldsm_x4(ah[mt],  base_s + sw);
                ldsm_x4(al2[mt], base_s + 16384u + sw);
            }
            #pragma unroll
            for (int np = 0; np < 4; np++) {
                uint32_t off = (uint32_t)((warpN * 64 + np * 16 + lrow) * 128 + ks * 32 + lchunk * 16);
                uint32_t sw = SMEM_SWIZZLE_128B(off);
                uint32_t bh[4], bl[4];
                ldsm_x4(bh, base_s + 32768u + sw);
                ldsm_x4(bl, base_s + 49152u + sw);
                #pragma unroll
                for (int mt = 0; mt < 2; mt++) {
                    mma_bf16(c[mt][2*np],   ah[mt],  bh[0], bh[2]);
                    mma_bf16(c[mt][2*np+1], ah[mt],  bh[1], bh[3]);
                    mma_bf16(c[mt][2*np],   ah[mt],  bl[0], bl[2]);
                    mma_bf16(c[mt][2*np+1], ah[mt],  bl[1], bl[3]);
                    mma_bf16(c[mt][2*np],   al2[mt], bh[0], bh[2]);
                    mma_bf16(c[mt][2*np+1], al2[mt], bh[1], bh[3]);
                }
            }
        }
    }
    __syncthreads();

    // epilogue: regs -> smem (padded) -> coalesced global
    float* sD = reinterpret_cast<float*>(smem);   // 128 x 129
    #pragma unroll
    for (int mt = 0; mt < 2; mt++) {
        #pragma unroll
        for (int nt = 0; nt < 8; nt++) {
            int r0 = warpM * 32 + mt * 16 + (lane >> 2);
            int col = warpN * 64 + nt * 8 + (lane & 3) * 2;
            sD[r0 * 129 + col]           = c[mt][nt][0];
            sD[r0 * 129 + col + 1]       = c[mt][nt][1];
            sD[(r0 + 8) * 129 + col]     = c[mt][nt][2];
            sD[(r0 + 8) * 129 + col + 1] = c[mt][nt][3];
        }
    }
    __syncthreads();

    for (int idx = tid; idx < 128 * 128; idx += 256) {
        int r = idx >> 7, cc = idx & 127;
        float v = sD[r * 129 + cc] + bias[bn + cc];
        size_t row = (size_t)(bm + r);
        int gc = bn + cc;
        if (mode == 0) {
            outF[row * N + gc] = v;
        } else if (mode == 1) {
            v = gelu_tanh(v);
            __nv_bfloat16 h, l; split_bf16(v, h, l);
            outHi[row * N + gc] = h;
            outLo[row * N + gc] = l;
        } else {
            if (gc < DM) {
                outF[row * DM + gc] = v * 0.125f;   // q, pre-scaled
            } else {
                __nv_bfloat16 h, l; split_bf16(v, h, l);
                size_t o = row * KVW + (gc - DM);
                outHi[o] = h; outLo[o] = l;
            }
        }
    }
}

// ================= HMMA sliding-window attention =================
// block = (c, h, b), 128 threads = 4 warps; warp handles 16 q-rows.
// smem: qh/ql 64x64, kh/kl 192x64, vh/vl 192x64 (all bf16, 128B rows, SW128).
#define AQH 0
#define AQL 8192
#define AKH 16384
#define AKL 40960
#define AVH 65536
#define AVL 90112
#define ATTN_SMEM 114688
__global__ void __launch_bounds__(128, 1)
attn_kernel(const float* __restrict__ qf,
            const __nv_bfloat16* __restrict__ kvh,
            const __nv_bfloat16* __restrict__ kvl,
            float* __restrict__ out) {
    extern __shared__ char smem[];
    const uint32_t sb = smem_to_u32(smem);
    const int c = blockIdx.x, h = blockIdx.y, b = blockIdx.z;
    const int tid = threadIdx.x, warp = tid >> 5, lane = tid & 31;

    // ---- load q (fp32, already scaled) -> split hi/lo into smem ----
    for (int idx = tid; idx < 64 * 16; idx += 128) {
        int r = idx >> 4, ch = idx & 15;
        float4 v = *reinterpret_cast<const float4*>(
            &qf[((size_t)b * SS + c * 64 + r) * DM + h * HD + ch * 4]);
        uint32_t off = SMEM_SWIZZLE_128B((uint32_t)(r * 128 + ch * 8));
        uint2 hh, ll;
        hh.x = pack_hi(v.x, v.y); hh.y = pack_hi(v.z, v.w);
        ll.x = pack_lo(v.x, v.y); ll.y = pack_lo(v.z, v.w);
        *reinterpret_cast<uint2*>(smem + AQH + off) = hh;
        *reinterpret_cast<uint2*>(smem + AQL + off) = ll;
    }
    // ---- load k/v hi/lo window (192 rows, zero-padded) ----
    for (int idx = tid; idx < 192 * 8; idx += 128) {
        int j = idx >> 3, ch = idx & 7;
        int g = c * 64 - 64 + j;
        uint4 z = {0, 0, 0, 0};
        uint4 kh4 = z, kl4 = z, vh4 = z, vl4 = z;
        if (g >= 0 && g < SS) {
            size_t rb = ((size_t)b * SS + g) * KVW + h * HD + ch * 8;
            kh4 = *reinterpret_cast<const uint4*>(&kvh[rb]);
            kl4 = *reinterpret_cast<const uint4*>(&kvl[rb]);
            vh4 = *reinterpret_cast<const uint4*>(&kvh[rb + DM]);
            vl4 = *reinterpret_cast<const uint4*>(&kvl[rb + DM]);
        }
        uint32_t off = SMEM_SWIZZLE_128B((uint32_t)(j * 128 + ch * 16));
        *reinterpret_cast<uint4*>(smem + AKH + off) = kh4;
        *reinterpret_cast<uint4*>(smem + AKL + off) = kl4;
        *reinterpret_cast<uint4*>(smem + AVH + off) = vh4;
        *reinterpret_cast<uint4*>(smem + AVL + off) = vl4;
    }
    __syncthreads();

    const int m0 = warp * 16;
    const int lrow = lane & 15;
    const int lch = lane >> 4;

    // ---- QK^T: 16 x 192 per warp, 3-term bf16 split ----
    float s[24][4];
    #pragma unroll
    for (int nt = 0; nt < 24; nt++)
        #pragma unroll
        for (int u = 0; u < 4; u++) s[nt][u] = 0.f;

    #pragma unroll
    for (int ks = 0; ks < 4; ks++) {
        uint32_t aoff = SMEM_SWIZZLE_128B((uint32_t)((m0 + lrow) * 128 + ks * 32 + lch * 16));
        uint32_t ah[4], al[4];
        ldsm_x4(ah, sb + AQH + aoff);
        ldsm_x4(al, sb + AQL + aoff);
        #pragma unroll
        for (int n6 = 0; n6 < 12; n6++) {
            uint32_t boff = SMEM_SWIZZLE_128B((uint32_t)((n6 * 16 + lrow) * 128 + ks * 32 + lch * 16));
            uint32_t bh[4], bl[4];
            ldsm_x4(bh, sb + AKH + boff);
            ldsm_x4(bl, sb + AKL + boff);
            mma_bf16(s[2*n6],   ah, bh[0], bh[2]);
            mma_bf16(s[2*n6+1], ah, bh[1], bh[3]);
            mma_bf16(s[2*n6],   ah, bl[0], bl[2]);
            mma_bf16(s[2*n6+1], ah, bl[1], bl[3]);
            mma_bf16(s[2*n6],   al, bh[0], bh[2]);
            mma_bf16(s[2*n6+1], al, bh[1], bh[3]);
        }
    }

    // ---- mask + softmax in registers (rows rA, rB per thread-quad) ----
    const int rA = m0 + (lane >> 2);
    const int rB = rA + 8;
    const int jb = 2 * (lane & 3);
    const int gof = c * 64 - 64;
    float mA = -INFINITY, mB = -INFINITY;
    #pragma unroll
    for (int nt = 0; nt < 24; nt++) {
        int j0 = nt * 8 + jb, j1 = j0 + 1;
        int g0 = gof + j0, g1 = gof + j1;
        bool in0 = (g0 >= 0) && (g0 < SS);
        bool in1 = (g1 >= 0) && (g1 < SS);
        if (!((j0 >= rA) && (j0 <= rA + 128) && in0)) s[nt][0] = -INFINITY;
        if (!((j1 >= rA) && (j1 <= rA + 128) && in1)) s[nt][1] = -INFINITY;
        if (!((j0 >= rB) && (j0 <= rB + 128) && in0)) s[nt][2] = -INFINITY;
        if (!((j1 >= rB) && (j1 <= rB + 128) && in1)) s[nt][3] = -INFINITY;
        mA = fmaxf(mA, fmaxf(s[nt][0], s[nt][1]));
        mB = fmaxf(mB, fmaxf(s[nt][2], s[nt][3]));
    }
    mA = fmaxf(mA, __shfl_xor_sync(0xffffffffu, mA, 1));
    mA = fmaxf(mA, __shfl_xor_sync(0xffffffffu, mA, 2));
    mB = fmaxf(mB, __shfl_xor_sync(0xffffffffu, mB, 1));
    mB = fmaxf(mB, __shfl_xor_sync(0xffffffffu, mB, 2));
    float sA = 0.f, sB = 0.f;
    #pragma unroll
    for (int nt = 0; nt < 24; nt++) {
        s[nt][0] = __expf(s[nt][0] - mA);
        s[nt][1] = __expf(s[nt][1] - mA);
        s[nt][2] = __expf(s[nt][2] - mB);
        s[nt][3] = __expf(s[nt][3] - mB);
        sA += s[nt][0] + s[nt][1];
        sB += s[nt][2] + s[nt][3];
    }
    sA += __shfl_xor_sync(0xffffffffu, sA, 1);
    sA += __shfl_xor_sync(0xffffffffu, sA, 2);
    sB += __shfl_xor_sync(0xffffffffu, sB, 1);
    sB += __shfl_xor_sync(0xffffffffu, sB, 2);
    const float invA = 1.0f / sA, invB = 1.0f / sB;

    // ---- PV: P (in-register repack to A-frags, hi/lo) x V (ldmatrix.trans) ----
    float o[8][4];
    #pragma unroll
    for (int nt = 0; nt < 8; nt++)
        #pragma unroll
        for (int u = 0; u < 4; u++) o[nt][u] = 0.f;

    #pragma unroll
    for (int t = 0; t < 12; t++) {
        uint32_t ph[4], pl[4];
        ph[0] = pack_hi(s[2*t][0],   s[2*t][1]);
        ph[1] = pack_hi(s[2*t][2],   s[2*t][3]);
        ph[2] = pack_hi(s[2*t+1][0], s[2*t+1][1]);
        ph[3] = pack_hi(s[2*t+1][2], s[2*t+1][3]);
        pl[0] = pack_lo(s[2*t][0],   s[2*t][1]);
        pl[1] = pack_lo(s[2*t][2],   s[2*t][3]);
        pl[2] = pack_lo(s[2*t+1][0], s[2*t+1][1]);
        pl[3] = pack_lo(s[2*t+1][2], s[2*t+1][3]);
        #pragma unroll
        for (int nn = 0; nn < 4; nn++) {
            uint32_t voff = SMEM_SWIZZLE_128B(
                (uint32_t)((t * 16 + (lane & 15)) * 128 + (nn * 16 + (lane >> 4) * 8) * 2));
            uint32_t vh[4], vl[4];
            ldsm_x4_trans(vh, sb + AVH + voff);
            ldsm_x4_trans(vl, sb + AVL + voff);
            mma_bf16(o[2*nn],   ph, vh[0], vh[1]);
            mma_bf16(o[2*nn+1], ph, vh[2], vh[3]);
            mma_bf16(o[2*nn],   ph, vl[0], vl[1]);
            mma_bf16(o[2*nn+1], ph, vl[2], vl[3]);
            mma_bf16(o[2*nn],   pl, vh[0], vh[1]);
            mma_bf16(o[2*nn+1], pl, vh[2], vh[3]);
        }
    }

    // ---- store (1/sum folded) ----
    const size_t rowg = (size_t)b * SS + c * 64;
    #pragma unroll
    for (int nt = 0; nt < 8; nt++) {
        int col = h * HD + nt * 8 + jb;
        float2 v0 = make_float2(o[nt][0] * invA, o[nt][1] * invA);
        float2 v1 = make_float2(o[nt][2] * invB, o[nt][3] * invB);
        *reinterpret_cast<float2*>(&out[(rowg + rA) * DM + col]) = v0;
        *reinterpret_cast<float2*>(&out[(rowg + rB) * DM + col]) = v1;
    }
}

// ================= warp-per-row residual + LayerNorm =================
__global__ void __launch_bounds__(256)
add_ln_kernel(const float* __restrict__ a,
              const float* __restrict__ r,
              const float* __restrict__ g,
              const float* __restrict__ beta,
              float* __restrict__ out,
              __nv_bfloat16* __restrict__ outHi,
              __nv_bfloat16* __restrict__ outLo) {
    const int warp = threadIdx.x >> 5, lane = threadIdx.x & 31;
    const int row = blockIdx.x * 8 + warp;
    const float4* pa = reinterpret_cast<const float4*>(a + (size_t)row * DM);
    const float4* pr = reinterpret_cast<const float4*>(r + (size_t)row * DM);
    const float4* pg = reinterpret_cast<const float4*>(g);
    const float4* pb = reinterpret_cast<const float4*>(beta);

    float4 v[6];
    float sum = 0.f;
    #pragma unroll
    for (int ch = 0; ch < 6; ch++) {
        float4 va = pa[lane + 32 * ch];
        float4 vr = pr[lane + 32 * ch];
        v[ch] = make_float4(va.x + vr.x, va.y + vr.y, va.z + vr.z, va.w + vr.w);
        sum += v[ch].x + v[ch].y + v[ch].z + v[ch].w;
    }
    #pragma unroll
    for (int o = 16; o > 0; o >>= 1) sum += __shfl_xor_sync(0xffffffffu, sum, o);
    float mu = sum * (1.0f / DM);

    float var = 0.f;
    #pragma unroll
    for (int ch = 0; ch < 6; ch++) {
        float dx = v[ch].x - mu, dy = v[ch].y - mu, dz = v[ch].z - mu, dw = v[ch].w - mu;
        var += dx * dx + dy * dy + dz * dz + dw * dw;
    }
    #pragma unroll
    for (int o = 16; o > 0; o >>= 1) var += __shfl_xor_sync(0xffffffffu, var, o);
    float rstd = rsqrtf(var * (1.0f / DM) + 1e-5f);

    float4* po = reinterpret_cast<float4*>(out + (size_t)row * DM);
    #pragma unroll
    for (int ch = 0; ch < 6; ch++) {
        float4 gg = pg[lane + 32 * ch];
        float4 bb = pb[lane + 32 * ch];
        float4 y;
        y.x = (v[ch].x - mu) * rstd * gg.x + bb.x;
        y.y = (v[ch].y - mu) * rstd * gg.y + bb.y;
        y.z = (v[ch].z - mu) * rstd * gg.z + bb.z;
        y.w = (v[ch].w - mu) * rstd * gg.w + bb.w;
        po[lane + 32 * ch] = y;
        if (outHi) {
            size_t o4 = (size_t)row * DM + (lane + 32 * ch) * 4;
            __nv_bfloat16 h0,l0,h1,l1,h2,l2,h3,l3;
            split_bf16(y.x, h0, l0); split_bf16(y.y, h1, l1);
            split_bf16(y.z, h2, l2); split_bf16(y.w, h3, l3);
            reinterpret_cast<__nv_bfloat162*>(outHi + o4)[0] = __nv_bfloat162(h0, h1);
            reinterpret_cast<__nv_bfloat162*>(outHi + o4)[1] = __nv_bfloat162(h2, h3);
            reinterpret_cast<__nv_bfloat162*>(outLo + o4)[0] = __nv_bfloat162(l0, l1);
            reinterpret_cast<__nv_bfloat162*>(outLo + o4)[1] = __nv_bfloat162(l2, l3);
        }
    }
}

// ================= launch =================
extern "C" void kernel_launch(void* const* d_in, const int* in_sizes, int n_in,
                              void* d_out, int out_size) {
    const float* x     = (const float*)d_in[0];
    const float* Wq    = (const float*)d_in[1];
    const float* bq    = (const float*)d_in[2];
    const float* Wk    = (const float*)d_in[3];
    const float* bk    = (const float*)d_in[4];
    const float* Wv    = (const float*)d_in[5];
    const float* bv    = (const float*)d_in[6];
    const float* ln1_g = (const float*)d_in[7];
    const float* ln1_b = (const float*)d_in[8];
    const float* W1    = (const float*)d_in[9];
    const float* b1    = (const float*)d_in[10];
    const float* W2    = (const float*)d_in[11];
    const float* b2    = (const float*)d_in[12];
    const float* ln2_g = (const float*)d_in[13];
    const float* ln2_b = (const float*)d_in[14];
    float* out = (float*)d_out;

    float *qf, *attn, *x1, *ff, *bqkv;
    __nv_bfloat16 *kvh, *kvl, *xh, *xl, *x1h, *x1l, *hidh, *hidl;
    __nv_bfloat16 *wqkvh, *wqkvl, *w1h, *w1l, *w2h, *w2l;
    cudaGetSymbolAddress((void**)&qf, g_qf);     cudaGetSymbolAddress((void**)&attn, g_attn);
    cudaGetSymbolAddress((void**)&x1, g_x1);     cudaGetSymbolAddress((void**)&ff, g_ff);
    cudaGetSymbolAddress((void**)&bqkv, g_bqkv);
    cudaGetSymbolAddress((void**)&kvh, g_kvh);   cudaGetSymbolAddress((void**)&kvl, g_kvl);
    cudaGetSymbolAddress((void**)&xh, g_xh);     cudaGetSymbolAddress((void**)&xl, g_xl);
    cudaGetSymbolAddress((void**)&x1h, g_x1h);   cudaGetSymbolAddress((void**)&x1l, g_x1l);
    cudaGetSymbolAddress((void**)&hidh, g_hidh); cudaGetSymbolAddress((void**)&hidl, g_hidl);
    cudaGetSymbolAddress((void**)&wqkvh, g_wqkvh); cudaGetSymbolAddress((void**)&wqkvl, g_wqkvl);
    cudaGetSymbolAddress((void**)&w1h, g_w1h);   cudaGetSymbolAddress((void**)&w1l, g_w1l);
    cudaGetSymbolAddress((void**)&w2h, g_w2h);   cudaGetSymbolAddress((void**)&w2l, g_w2l);

    cudaFuncSetAttribute(tc_gemm, cudaFuncAttributeMaxDynamicSharedMemorySize, GEMM_SMEM);
    cudaFuncSetAttribute(attn_kernel, cudaFuncAttributeMaxDynamicSharedMemorySize, ATTN_SMEM);

    // ---- convert inputs ----
    {
        int n4 = MROWS * DM / 4;
        split_convert<<<(n4 + 255) / 256, 256>>>(x, xh, xl, n4);
        pack_bias3<<<(QKVN + 255) / 256, 256>>>(bq, bk, bv, bqkv);
        dim3 tb(32, 8);
        transpose_convert<<<dim3(DM / 32, DM / 32), tb>>>(Wq, wqkvh,               wqkvl,               DM, DM);
        transpose_convert<<<dim3(DM / 32, DM / 32), tb>>>(Wk, wqkvh + DM * DM,     wqkvl + DM * DM,     DM, DM);
        transpose_convert<<<dim3(DM / 32, DM / 32), tb>>>(Wv, wqkvh + 2 * DM * DM, wqkvl + 2 * DM * DM, DM, DM);
        transpose_convert<<<dim3(FF / 32, DM / 32), tb>>>(W1, w1h, w1l, DM, FF);
        transpose_convert<<<dim3(DM / 32, FF / 32), tb>>>(W2, w2h, w2l, FF, DM);
    }

    // ---- fused QKV projection: q fp32 (scaled), k/v bf16 hi/lo ----
    {
        dim3 grid(QKVN / 128, MROWS / 128);
        tc_gemm<<<grid, 256, GEMM_SMEM>>>(xh, xl, wqkvh, wqkvl, bqkv, qf,
                                          kvh, kvl, MROWS, QKVN, DM, 2);
    }

    // ---- attention (HMMA) ----
    {
        dim3 grid(NC, NH, BB);
        attn_kernel<<<grid, 128, ATTN_SMEM>>>(qf, kvh, kvl, attn);
    }

    // ---- x1 = LN(attn + x), emit bf16 hi/lo ----
    add_ln_kernel<<<MROWS / 8, 256>>>(attn, x, ln1_g, ln1_b, x1, x1h, x1l);

    // ---- FFN ----
    {
        dim3 grid1(FF / 128, MROWS / 128);
        tc_gemm<<<grid1, 256, GEMM_SMEM>>>(x1h, x1l, w1h, w1l, b1, nullptr,
                                           hidh, hidl, MROWS, FF, DM, 1);
        dim3 grid2(DM / 128, MROWS / 128);
        tc_gemm<<<grid2, 256, GEMM_SMEM>>>(hidh, hidl, w2h, w2l, b2, ff,
                                           nullptr, nullptr, MROWS, DM, FF, 0);
    }

    // ---- out = LN(ff + x1) ----
    add_ln_kernel<<<MROWS / 8, 256>>>(ff, x1, ln2_g, ln2_b, out, nullptr, nullptr);
}